// round 8
// baseline (speedup 1.0000x reference)
#include <cuda_runtime.h>
#include <cuda_fp16.h>
#include <cstdint>

#define B_   32768
#define D_   1472
#define E_   8
#define H1_  512
#define H2_  256
#define T_   2
#define NSLAB 256          // one stats slab per 128-row m-block
#define NTILE 256          // CTA tile N

// ---------------- scratch (static device arrays; no cudaMalloc) ------------
__device__ float g_h1[(size_t)E_ * B_ * H1_];
__device__ float g_h2[(size_t)E_ * B_ * H2_];
__device__ float g_gates[(size_t)T_ * B_ * E_];
__device__ float g_psum[(size_t)E_ * H1_ * NSLAB];
__device__ float g_psq [(size_t)E_ * H1_ * NSLAB];
__device__ float g_s1[E_ * H1_], g_t1[E_ * H1_];
__device__ float g_s2[E_ * H2_], g_t2[E_ * H2_];
// fp16 pre-splits: x -> hi+lo pair; weights -> hi only
__device__ __half g_xh[(size_t)B_ * D_];
__device__ __half g_xl[(size_t)B_ * D_];
__device__ __half g_w1h[(size_t)E_ * D_ * H1_];
__device__ __half g_w2h[(size_t)E_ * H1_ * H2_];

// ---------------- PTX helpers ----------------------------------------------
__device__ __forceinline__ uint32_t s2u(const void* p) {
    return (uint32_t)__cvta_generic_to_shared(p);
}
__device__ __forceinline__ void ldsm_x4(uint32_t* r, uint32_t a) {
    asm volatile("ldmatrix.sync.aligned.m8n8.x4.shared.b16 {%0,%1,%2,%3}, [%4];"
        : "=r"(r[0]), "=r"(r[1]), "=r"(r[2]), "=r"(r[3]) : "r"(a));
}
__device__ __forceinline__ void ldsm_x4t(uint32_t* r, uint32_t a) {
    asm volatile("ldmatrix.sync.aligned.m8n8.x4.trans.shared.b16 {%0,%1,%2,%3}, [%4];"
        : "=r"(r[0]), "=r"(r[1]), "=r"(r[2]), "=r"(r[3]) : "r"(a));
}
__device__ __forceinline__ void mma16816(float* d, const uint32_t* a, const uint32_t* b) {
    asm volatile("mma.sync.aligned.m16n8k16.row.col.f32.f16.f16.f32 "
        "{%0,%1,%2,%3}, {%4,%5,%6,%7}, {%8,%9}, {%0,%1,%2,%3};"
        : "+f"(d[0]), "+f"(d[1]), "+f"(d[2]), "+f"(d[3])
        : "r"(a[0]), "r"(a[1]), "r"(a[2]), "r"(a[3]), "r"(b[0]), "r"(b[1]));
}
__device__ __forceinline__ void cp16(uint32_t dst, const void* src) {
    asm volatile("cp.async.cg.shared.global [%0], [%1], 16;"
        :: "r"(dst), "l"(src) : "memory");
}
__device__ __forceinline__ void cp_commit() {
    asm volatile("cp.async.commit_group;" ::: "memory");
}
__device__ __forceinline__ void cp_wait0() {
    asm volatile("cp.async.wait_group 0;" ::: "memory");
}

// fp32 -> fp16 hi + fp16 residual lo, packed pairs
__device__ __forceinline__ void split_pair_h(float x, float y,
                                             uint32_t& hi, uint32_t& lo) {
    __half hx = __float2half_rn(x);
    __half hy = __float2half_rn(y);
    __half lx = __float2half_rn(x - __half2float(hx));
    __half ly = __float2half_rn(y - __half2float(hy));
    __half2 h = __halves2half2(hx, hy);
    __half2 l = __halves2half2(lx, ly);
    hi = *reinterpret_cast<uint32_t*>(&h);
    lo = *reinterpret_cast<uint32_t*>(&l);
}

// ---------------- SMEM layout (bytes), 2 stages ------------------------------
// A tiles: 128 rows x 32 fp16, padded row = 40 elems (80 B)  -> 10240 B each
// B tile : 32 rows x 256 fp16, padded row = 264 elems (528B) -> 16896 B
#define ASTR 40
#define BSTRE 264
#define STG_SZ 37376
#define AH_(b) ((b) * STG_SZ)
#define AL_(b) ((b) * STG_SZ + 10240)
#define BH_(b) ((b) * STG_SZ + 20480)
#define SMEM_BYTES (2 * STG_SZ)   // 74752 -> 1 CTA of 512 thr per SM

// ---------------------------------------------------------------------------
// fp16 2-product HMMA GEMM: D = (ah+al)*bh, 2-stage cp.async, 512 threads,
// CTA tile 128x256 (halves A-side L2 traffic), warp tile m32 x n64,
// fused deterministic BN batch stats in the epilogue.
// ---------------------------------------------------------------------------
template<int K_TOT, int N_TOT, int ASRC>
__global__ __launch_bounds__(512, 1) void gemm_hmma(
    const float* __restrict__ bias_all)
{
    extern __shared__ char smem[];
    __shared__ float sred_s[4][NTILE];
    __shared__ float sred_q[4][NTILE];
    const uint32_t sb = s2u(smem);
    const int tid  = threadIdx.x;
    const int lane = tid & 31;
    const int wid  = tid >> 5;
    const int wm   = (wid & 3) * 32;   // 4 warp rows of 32
    const int wn   = (wid >> 2) * 64;  // 4 warp cols of 64

    constexpr int NB = N_TOT / NTILE;
    const int e  = blockIdx.x / NB;
    const int bn = (blockIdx.x % NB) * NTILE;
    const int bm = blockIdx.y * 128;

    const __half* Ah = g_xh + (size_t)bm * K_TOT;                   // ASRC==0
    const __half* Al = g_xl + (size_t)bm * K_TOT;
    const float* Af = g_h1 + ((size_t)e * B_ + bm) * (size_t)K_TOT; // ASRC==1
    const __half* Wh =
        ((ASRC == 0) ? g_w1h : g_w2h) + (size_t)e * K_TOT * N_TOT + bn;
    const float* S  = g_s1 + e * K_TOT;
    const float* Tt = g_t1 + e * K_TOT;

    float acc[2][8][4];
    #pragma unroll
    for (int i = 0; i < 2; ++i)
        #pragma unroll
        for (int j = 0; j < 8; ++j)
            #pragma unroll
            for (int r = 0; r < 4; ++r) acc[i][j][r] = 0.f;

    constexpr int NT = K_TOT / 32;
    float4 av[2];   // ASRC==1 register staging

    #define CP_A_STAGE(stg, k0)                                              \
        do {                                                                 \
            _Pragma("unroll")                                                \
            for (int i = 0; i < 2; ++i) {                                    \
                int c = tid + i * 512, cc = c & 511;                         \
                int row = cc >> 2, k4 = cc & 3;                              \
                const __half* src = ((c < 512) ? Ah : Al)                    \
                                    + (size_t)row * K_TOT + (k0) + k4 * 8;   \
                cp16(sb + ((c < 512) ? AH_(stg) : AL_(stg))                  \
                        + row * 80 + k4 * 16, src);                          \
            }                                                                \
        } while (0)
    #define CP_B_STAGE(stg, k0)                                              \
        do {                                                                 \
            _Pragma("unroll")                                                \
            for (int i = 0; i < 2; ++i) {                                    \
                int cc = tid + i * 512;                                      \
                int kr = cc >> 5, n16 = cc & 31;                             \
                cp16(sb + BH_(stg) + kr * 528 + n16 * 16,                    \
                     Wh + (size_t)((k0) + kr) * N_TOT + n16 * 8);            \
            }                                                                \
        } while (0)
    #define LDG_AV(k0)                                                       \
        do {                                                                 \
            _Pragma("unroll")                                                \
            for (int i = 0; i < 2; ++i) {                                    \
                int idx = tid + i * 512;                                     \
                av[i] = *(const float4*)(Af + (size_t)(idx >> 3) * K_TOT     \
                                            + (k0) + (idx & 7) * 4);         \
            }                                                                \
        } while (0)
    #define STS_AV(stg, k0)                                                  \
        do {                                                                 \
            __half* aH = (__half*)(smem + AH_(stg));                         \
            __half* aL = (__half*)(smem + AL_(stg));                         \
            _Pragma("unroll")                                                \
            for (int i = 0; i < 2; ++i) {                                    \
                int idx = tid + i * 512;                                     \
                int row = idx >> 3, c4 = (idx & 7) * 4;                      \
                float4 v = av[i];                                            \
                int kc = (k0) + c4;                                          \
                float4 s4 = *(const float4*)(S + kc);                        \
                float4 t4 = *(const float4*)(Tt + kc);                       \
                v.x = fmaxf(0.f, fmaf(v.x, s4.x, t4.x));                     \
                v.y = fmaxf(0.f, fmaf(v.y, s4.y, t4.y));                     \
                v.z = fmaxf(0.f, fmaf(v.z, s4.z, t4.z));                     \
                v.w = fmaxf(0.f, fmaf(v.w, s4.w, t4.w));                     \
                uint32_t h0, l0, h1, l1;                                     \
                split_pair_h(v.x, v.y, h0, l0);                              \
                split_pair_h(v.z, v.w, h1, l1);                              \
                int off = row * ASTR + c4;                                   \
                *(uint32_t*)&aH[off]     = h0;                               \
                *(uint32_t*)&aH[off + 2] = h1;                               \
                *(uint32_t*)&aL[off]     = l0;                               \
                *(uint32_t*)&aL[off + 2] = l1;                               \
            }                                                                \
        } while (0)

    // ============ prologue: stage 0 in flight ============
    if (ASRC == 0) {
        CP_A_STAGE(0, 0);
    } else {
        LDG_AV(0);
    }
    CP_B_STAGE(0, 0);
    cp_commit();

    // ============ main loop (2-stage, R6 schedule) ============
    for (int kt = 0; kt < NT; ++kt) {
        const int cur = kt & 1;

        if (ASRC == 1) {
            STS_AV(cur, kt * 32);   // safe: buffer last read in iter kt-2
        }
        cp_wait0();                 // drains stage kt (issued in iter kt-1)
        __syncthreads();

        // ---- prefetch stage kt+1 (one full iteration of slack)
        if (kt + 1 < NT) {
            const int nxt = (kt + 1) & 1;
            const int k0n = (kt + 1) * 32;
            if (ASRC == 0) CP_A_STAGE(nxt, k0n);
            else           LDG_AV(k0n);
            CP_B_STAGE(nxt, k0n);
            cp_commit();
        }

        // ---- MMAs on stage cur
        const __half* aH = (const __half*)(smem + AH_(cur));
        const __half* aL = (const __half*)(smem + AL_(cur));
        const __half* bH = (const __half*)(smem + BH_(cur));
        #pragma unroll
        for (int ks = 0; ks < 2; ++ks) {
            const int k0s = ks * 16;
            uint32_t bh[4][4];
            #pragma unroll
            for (int g = 0; g < 4; ++g) {
                int r = k0s + (lane & 15);
                int c = wn + g * 16 + (lane >> 4) * 8;
                ldsm_x4t(bh[g], s2u(&bH[r * BSTRE + c]));
            }
            #pragma unroll
            for (int mi = 0; mi < 2; ++mi) {
                uint32_t ah[4], al[4];
                int r = wm + mi * 16 + (lane & 15);
                int c = k0s + (lane >> 4) * 8;
                ldsm_x4(ah, s2u(&aH[r * ASTR + c]));
                ldsm_x4(al, s2u(&aL[r * ASTR + c]));
                #pragma unroll
                for (int ni = 0; ni < 8; ++ni) {
                    const uint32_t* pb = &bh[ni >> 1][(ni & 1) * 2];
                    mma16816(acc[mi][ni], ah, pb);
                    mma16816(acc[mi][ni], al, pb);
                }
            }
        }
        __syncthreads();
    }

    // ---- epilogue: +bias, store, fused BN stats (deterministic)
    float* C = ((ASRC == 0) ? g_h1 : g_h2) + ((size_t)e * B_ + bm) * N_TOT + bn;
    const float* bias = bias_all + e * N_TOT + bn;
    #pragma unroll
    for (int ni = 0; ni < 8; ++ni) {
        int c0 = wn + ni * 8 + (lane & 3) * 2;
        float b0 = bias[c0], b1 = bias[c0 + 1];
        float ss0 = 0.f, ss1 = 0.f, qq0 = 0.f, qq1 = 0.f;
        #pragma unroll
        for (int mi = 0; mi < 2; ++mi) {
            int r0 = wm + mi * 16 + (lane >> 2);
            float v00 = acc[mi][ni][0] + b0, v01 = acc[mi][ni][1] + b1;
            float v10 = acc[mi][ni][2] + b0, v11 = acc[mi][ni][3] + b1;
            float2 w0 = { v00, v01 }, w1 = { v10, v11 };
            *(float2*)(C + (size_t)r0 * N_TOT + c0) = w0;
            *(float2*)(C + (size_t)(r0 + 8) * N_TOT + c0) = w1;
            ss0 += v00 + v10;  ss1 += v01 + v11;
            qq0 += v00 * v00 + v10 * v10;
            qq1 += v01 * v01 + v11 * v11;
        }
        #pragma unroll
        for (int o = 4; o < 32; o <<= 1) {
            ss0 += __shfl_xor_sync(0xffffffffu, ss0, o);
            ss1 += __shfl_xor_sync(0xffffffffu, ss1, o);
            qq0 += __shfl_xor_sync(0xffffffffu, qq0, o);
            qq1 += __shfl_xor_sync(0xffffffffu, qq1, o);
        }
        if (lane < 4) {
            int c = wn + ni * 8 + lane * 2;
            int rg = wid & 3;
            sred_s[rg][c] = ss0; sred_s[rg][c + 1] = ss1;
            sred_q[rg][c] = qq0; sred_q[rg][c + 1] = qq1;
        }
    }
    __syncthreads();
    if (tid < NTILE) {
        float s = sred_s[0][tid] + sred_s[1][tid] + sred_s[2][tid] + sred_s[3][tid];
        float q = sred_q[0][tid] + sred_q[1][tid] + sred_q[2][tid] + sred_q[3][tid];
        size_t idx = ((size_t)e * N_TOT + bn + tid) * NSLAB + blockIdx.y;
        g_psum[idx] = s;
        g_psq[idx]  = q;
    }
}

// ---------------------------------------------------------------------------
// fp32 -> fp16 hi/lo split (x) and fp32 -> fp16 round (weights)
// ---------------------------------------------------------------------------
__global__ __launch_bounds__(256) void split_f16(
    const float* __restrict__ src, __half* __restrict__ dh,
    __half* __restrict__ dl, size_t n8)
{
    size_t i = (size_t)blockIdx.x * 256 + threadIdx.x;
    if (i >= n8) return;
    const float4* s = (const float4*)src + i * 2;
    float4 v0 = s[0], v1 = s[1];
    uint4 h, l;
    split_pair_h(v0.x, v0.y, h.x, l.x);
    split_pair_h(v0.z, v0.w, h.y, l.y);
    split_pair_h(v1.x, v1.y, h.z, l.z);
    split_pair_h(v1.z, v1.w, h.w, l.w);
    ((uint4*)dh)[i] = h;
    ((uint4*)dl)[i] = l;
}

__global__ __launch_bounds__(256) void round_f16(
    const float* __restrict__ src, __half* __restrict__ dh, size_t n8)
{
    size_t i = (size_t)blockIdx.x * 256 + threadIdx.x;
    if (i >= n8) return;
    const float4* s = (const float4*)src + i * 2;
    float4 v0 = s[0], v1 = s[1];
    __half2 h0 = __floats2half2_rn(v0.x, v0.y);
    __half2 h1 = __floats2half2_rn(v0.z, v0.w);
    __half2 h2 = __floats2half2_rn(v1.x, v1.y);
    __half2 h3 = __floats2half2_rn(v1.z, v1.w);
    uint4 h = { *(uint32_t*)&h0, *(uint32_t*)&h1, *(uint32_t*)&h2, *(uint32_t*)&h3 };
    ((uint4*)dh)[i] = h;
}

// ---------------------------------------------------------------------------
// Gates (measured 140us): 4 rows per warp, scalar X loads.
// ---------------------------------------------------------------------------
__global__ __launch_bounds__(256) void gates_kernel(
    const float* __restrict__ X, const float* __restrict__ Wg,
    const float* __restrict__ bg)
{
    int warp = (blockIdx.x * blockDim.x + threadIdx.x) >> 5;
    int lane = threadIdx.x & 31;
    int r0 = warp * 4;
    if (r0 >= B_) return;
    const float* x0 = X + (size_t)(r0 + 0) * D_;
    const float* x1 = X + (size_t)(r0 + 1) * D_;
    const float* x2 = X + (size_t)(r0 + 2) * D_;
    const float* x3 = X + (size_t)(r0 + 3) * D_;

    float acc[4][16];
    #pragma unroll
    for (int r = 0; r < 4; ++r)
        #pragma unroll
        for (int i = 0; i < 16; ++i) acc[r][i] = 0.f;

    for (int d = lane; d < D_; d += 32) {
        float xv0 = x0[d], xv1 = x1[d], xv2 = x2[d], xv3 = x3[d];
        #pragma unroll
        for (int t = 0; t < T_; ++t) {
            const float* wr = Wg + ((size_t)t * D_ + d) * E_;
            float4 w0 = *(const float4*)wr;
            float4 w1 = *(const float4*)(wr + 4);
            float wv[8] = { w0.x, w0.y, w0.z, w0.w, w1.x, w1.y, w1.z, w1.w };
            #pragma unroll
            for (int ee = 0; ee < 8; ++ee) {
                acc[0][t*8+ee] = fmaf(xv0, wv[ee], acc[0][t*8+ee]);
                acc[1][t*8+ee] = fmaf(xv1, wv[ee], acc[1][t*8+ee]);
                acc[2][t*8+ee] = fmaf(xv2, wv[ee], acc[2][t*8+ee]);
                acc[3][t*8+ee] = fmaf(xv3, wv[ee], acc[3][t*8+ee]);
            }
        }
    }
    #pragma unroll
    for (int r = 0; r < 4; ++r)
        #pragma unroll
        for (int i = 0; i < 16; ++i)
            #pragma unroll
            for (int o = 16; o > 0; o >>= 1)
                acc[r][i] += __shfl_xor_sync(0xffffffffu, acc[r][i], o);

    if (lane < 4) {
        #pragma unroll
        for (int r = 0; r < 4; ++r) {
            if (lane == r) {
                #pragma unroll
                for (int t = 0; t < T_; ++t) {
                    float v[8], m = -1e30f;
                    #pragma unroll
                    for (int e = 0; e < 8; ++e) {
                        v[e] = acc[r][t*8+e] + bg[t*8+e];
                        m = fmaxf(m, v[e]);
                    }
                    float s = 0.f;
                    #pragma unroll
                    for (int e = 0; e < 8; ++e) { v[e] = expf(v[e] - m); s += v[e]; }
                    float inv = 1.f / s;
                    #pragma unroll
                    for (int e = 0; e < 8; ++e)
                        g_gates[((size_t)t * B_ + r0 + r) * E_ + e] = v[e] * inv;
                }
            }
        }
    }
}

// ---------------------------------------------------------------------------
// Combine per-mblock stats -> BN scale/shift (deterministic, 256 slabs)
// ---------------------------------------------------------------------------
__global__ __launch_bounds__(256) void stats_combine(
    int which, int Hc, const float* __restrict__ gamma,
    const float* __restrict__ beta)
{
    int i = blockIdx.x * 256 + threadIdx.x;
    if (i >= E_ * Hc) return;
    const float* ps = g_psum + (size_t)i * NSLAB;
    const float* pq = g_psq  + (size_t)i * NSLAB;
    float s = 0.f, q = 0.f;
    for (int j = 0; j < NSLAB; ++j) { s += ps[j]; q += pq[j]; }
    const float invB = 1.f / (float)B_;
    float mu  = s * invB;
    float var = q * invB - mu * mu;
    float inv = rsqrtf(var + 1e-5f);
    float gg = gamma[i], bb = beta[i];
    float* Sd = (which == 0) ? g_s1 : g_s2;
    float* Td = (which == 0) ? g_t1 : g_t2;
    Sd[i] = gg * inv;
    Td[i] = bb - gg * mu * inv;
}

// ---------------------------------------------------------------------------
// Final: out[t,b,e*H2+k] = relu(BN2(g_h2[e,b,k])) * gates[t,b,e]
// ---------------------------------------------------------------------------
__global__ __launch_bounds__(256) void final_kernel(float* __restrict__ out)
{
    size_t idx = (size_t)blockIdx.x * blockDim.x + threadIdx.x;
    int k4 = (int)(idx & 63);
    int b  = (int)((idx >> 6) & (B_ - 1));
    int e  = (int)(idx >> 21);
    int k  = k4 * 4;

    float4 h  = *(const float4*)(g_h2 + (((size_t)e * B_ + b) * H2_ + k));
    float4 s  = *(const float4*)(g_s2 + e * H2_ + k);
    float4 tt = *(const float4*)(g_t2 + e * H2_ + k);
    float4 y;
    y.x = fmaxf(0.f, fmaf(h.x, s.x, tt.x));
    y.y = fmaxf(0.f, fmaf(h.y, s.y, tt.y));
    y.z = fmaxf(0.f, fmaf(h.z, s.z, tt.z));
    y.w = fmaxf(0.f, fmaf(h.w, s.w, tt.w));

    float ga = g_gates[(size_t)b * E_ + e];
    float gb = g_gates[(size_t)B_ * E_ + (size_t)b * E_ + e];

    size_t o0 = (size_t)b * (E_ * H2_) + e * H2_ + k;
    size_t o1 = (size_t)B_ * (E_ * H2_) + o0;
    float4 v0 = { y.x * ga, y.y * ga, y.z * ga, y.w * ga };
    float4 v1 = { y.x * gb, y.y * gb, y.z * gb, y.w * gb };
    *(float4*)(out + o0) = v0;
    *(float4*)(out + o1) = v1;
}

// ---------------------------------------------------------------------------
extern "C" void kernel_launch(void* const* d_in, const int* in_sizes, int n_in,
                              void* d_out, int out_size)
{
    const float* x   = (const float*)d_in[0];
    const float* W1  = (const float*)d_in[1];
    const float* b1  = (const float*)d_in[2];
    const float* g1  = (const float*)d_in[3];
    const float* be1 = (const float*)d_in[4];
    const float* W2  = (const float*)d_in[5];
    const float* b2  = (const float*)d_in[6];
    const float* g2  = (const float*)d_in[7];
    const float* be2 = (const float*)d_in[8];
    const float* Wg  = (const float*)d_in[9];
    const float* bg  = (const float*)d_in[10];
    float* out = (float*)d_out;

    cudaFuncSetAttribute(gemm_hmma<D_, H1_, 0>,
        cudaFuncAttributeMaxDynamicSharedMemorySize, SMEM_BYTES);
    cudaFuncSetAttribute(gemm_hmma<H1_, H2_, 1>,
        cudaFuncAttributeMaxDynamicSharedMemorySize, SMEM_BYTES);

    // ---- pre-splits / rounds
    {
        __half *xh, *xl, *w1h, *w2h;
        cudaGetSymbolAddress((void**)&xh,  g_xh);
        cudaGetSymbolAddress((void**)&xl,  g_xl);
        cudaGetSymbolAddress((void**)&w1h, g_w1h);
        cudaGetSymbolAddress((void**)&w2h, g_w2h);
        size_t nx = (size_t)B_ * D_ / 8;
        size_t n1 = (size_t)E_ * D_ * H1_ / 8;
        size_t n2 = (size_t)E_ * H1_ * H2_ / 8;
        split_f16<<<(unsigned)((nx + 255) / 256), 256>>>(x, xh, xl, nx);
        round_f16<<<(unsigned)((n1 + 255) / 256), 256>>>(W1, w1h, n1);
        round_f16<<<(unsigned)((n2 + 255) / 256), 256>>>(W2, w2h, n2);
    }

    gates_kernel<<<B_ / 32, 256>>>(x, Wg, bg);

    gemm_hmma<D_, H1_, 0>
        <<<dim3((H1_ / NTILE) * E_, B_ / 128), 512, SMEM_BYTES>>>(b1);
    stats_combine<<<(E_ * H1_ + 255) / 256, 256>>>(0, H1_, g1, be1);

    gemm_hmma<H1_, H2_, 1>
        <<<dim3((H2_ / NTILE) * E_, B_ / 128), 512, SMEM_BYTES>>>(b2);
    stats_combine<<<(E_ * H2_ + 255) / 256, 256>>>(1, H2_, g2, be2);

    final_kernel<<<(unsigned)((size_t)E_ * B_ * (H2_ / 4) / 256), 256>>>(out);
}

// round 9
// speedup vs baseline: 1.5751x; 1.5751x over previous
#include <cuda_runtime.h>
#include <cuda_fp16.h>
#include <cstdint>

#define B_   32768
#define D_   1472
#define E_   8
#define H1_  512
#define H2_  256
#define T_   2
#define NSLAB 256          // one stats slab per 128-row m-block

// ---------------- scratch (static device arrays; no cudaMalloc) ------------
__device__ float g_h1[(size_t)E_ * B_ * H1_];
__device__ float g_h2[(size_t)E_ * B_ * H2_];
__device__ float g_gates[(size_t)T_ * B_ * E_];
__device__ float g_psum[(size_t)E_ * H1_ * NSLAB];
__device__ float g_psq [(size_t)E_ * H1_ * NSLAB];
__device__ float g_s1[E_ * H1_], g_t1[E_ * H1_];
__device__ float g_s2[E_ * H2_], g_t2[E_ * H2_];
// fp16 rounded operands
__device__ __half g_xh[(size_t)B_ * D_];
__device__ __half g_w1h[(size_t)E_ * D_ * H1_];
__device__ __half g_w2h[(size_t)E_ * H1_ * H2_];

// ---------------- PTX helpers ----------------------------------------------
__device__ __forceinline__ uint32_t s2u(const void* p) {
    return (uint32_t)__cvta_generic_to_shared(p);
}
__device__ __forceinline__ void ldsm_x4(uint32_t* r, uint32_t a) {
    asm volatile("ldmatrix.sync.aligned.m8n8.x4.shared.b16 {%0,%1,%2,%3}, [%4];"
        : "=r"(r[0]), "=r"(r[1]), "=r"(r[2]), "=r"(r[3]) : "r"(a));
}
__device__ __forceinline__ void ldsm_x4t(uint32_t* r, uint32_t a) {
    asm volatile("ldmatrix.sync.aligned.m8n8.x4.trans.shared.b16 {%0,%1,%2,%3}, [%4];"
        : "=r"(r[0]), "=r"(r[1]), "=r"(r[2]), "=r"(r[3]) : "r"(a));
}
__device__ __forceinline__ void mma16816(float* d, const uint32_t* a, const uint32_t* b) {
    asm volatile("mma.sync.aligned.m16n8k16.row.col.f32.f16.f16.f32 "
        "{%0,%1,%2,%3}, {%4,%5,%6,%7}, {%8,%9}, {%0,%1,%2,%3};"
        : "+f"(d[0]), "+f"(d[1]), "+f"(d[2]), "+f"(d[3])
        : "r"(a[0]), "r"(a[1]), "r"(a[2]), "r"(a[3]), "r"(b[0]), "r"(b[1]));
}
__device__ __forceinline__ void cp16(uint32_t dst, const void* src) {
    asm volatile("cp.async.cg.shared.global [%0], [%1], 16;"
        :: "r"(dst), "l"(src) : "memory");
}
__device__ __forceinline__ void cp_commit() {
    asm volatile("cp.async.commit_group;" ::: "memory");
}
__device__ __forceinline__ void cp_wait0() {
    asm volatile("cp.async.wait_group 0;" ::: "memory");
}

// ---------------- SMEM layout (bytes), 2 stages ------------------------------
// A tile: 128 rows x 32 fp16, padded row = 40 elems (80 B)  -> 10240 B
// B tile: 32 rows x 128 fp16, padded row = 136 elems (272B) ->  8704 B
#define ASTR 40
#define BSTR 136
#define STG_SZ 18944
#define AH_(b) ((b) * STG_SZ)
#define BH_(b) ((b) * STG_SZ + 10240)
#define SMEM_BYTES (2 * STG_SZ)   // 37888 -> 2 CTAs/SM easily

// ---------------------------------------------------------------------------
// Pure fp16 HMMA GEMM (single product), 2-stage cp.async, 2 CTAs/SM,
// warp tile m32 x n64, fused deterministic BN batch stats in the epilogue.
//  ASRC 0: A = g_xh (fp16-rounded x), C -> g_h1, W -> g_w1h
//  ASRC 1: A = relu(BN1(g_h1)) fused during staging, C -> g_h2, W -> g_w2h
// ---------------------------------------------------------------------------
template<int K_TOT, int N_TOT, int ASRC, int NB>
__global__ __launch_bounds__(256, 2) void gemm_hmma(
    const float* __restrict__ bias_all)
{
    extern __shared__ char smem[];
    __shared__ float sred_s[4][128];
    __shared__ float sred_q[4][128];
    const uint32_t sb = s2u(smem);
    const int tid  = threadIdx.x;
    const int lane = tid & 31;
    const int wid  = tid >> 5;
    const int wm   = (wid & 3) * 32;   // 4 warp rows of 32
    const int wn   = (wid >> 2) * 64;  // 2 warp cols of 64

    const int e  = blockIdx.x / NB;
    const int bn = (blockIdx.x % NB) * 128;
    const int bm = blockIdx.y * 128;

    const __half* Ah = g_xh + (size_t)bm * K_TOT;                   // ASRC==0
    const float* Af = g_h1 + ((size_t)e * B_ + bm) * (size_t)K_TOT; // ASRC==1
    const __half* Wh =
        ((ASRC == 0) ? g_w1h : g_w2h) + (size_t)e * K_TOT * N_TOT + bn;
    const float* S  = g_s1 + e * K_TOT;
    const float* Tt = g_t1 + e * K_TOT;

    float acc[2][8][4];
    #pragma unroll
    for (int i = 0; i < 2; ++i)
        #pragma unroll
        for (int j = 0; j < 8; ++j)
            #pragma unroll
            for (int r = 0; r < 4; ++r) acc[i][j][r] = 0.f;

    constexpr int NT = K_TOT / 32;
    float4 av[4];   // ASRC==1 register staging

    #define CP_A_STAGE(stg, k0)                                              \
        do {                                                                 \
            _Pragma("unroll")                                                \
            for (int i = 0; i < 2; ++i) {                                    \
                int cc = tid + i * 256;                                      \
                int row = cc >> 2, k4 = cc & 3;                              \
                cp16(sb + AH_(stg) + row * 80 + k4 * 16,                     \
                     Ah + (size_t)row * K_TOT + (k0) + k4 * 8);              \
            }                                                                \
        } while (0)
    #define CP_B_STAGE(stg, k0)                                              \
        do {                                                                 \
            _Pragma("unroll")                                                \
            for (int i = 0; i < 2; ++i) {                                    \
                int cc = tid + i * 256;                                      \
                int kr = cc >> 4, n16 = cc & 15;                             \
                cp16(sb + BH_(stg) + kr * 272 + n16 * 16,                    \
                     Wh + (size_t)((k0) + kr) * N_TOT + n16 * 8);            \
            }                                                                \
        } while (0)
    #define LDG_AV(k0)                                                       \
        do {                                                                 \
            _Pragma("unroll")                                                \
            for (int i = 0; i < 4; ++i) {                                    \
                int idx = tid + i * 256;                                     \
                av[i] = *(const float4*)(Af + (size_t)(idx >> 3) * K_TOT     \
                                            + (k0) + (idx & 7) * 4);         \
            }                                                                \
        } while (0)
    #define STS_AV(stg, k0)                                                  \
        do {                                                                 \
            __half* aH = (__half*)(smem + AH_(stg));                         \
            _Pragma("unroll")                                                \
            for (int i = 0; i < 4; ++i) {                                    \
                int idx = tid + i * 256;                                     \
                int row = idx >> 3, c4 = (idx & 7) * 4;                      \
                float4 v = av[i];                                            \
                int kc = (k0) + c4;                                          \
                float4 s4 = *(const float4*)(S + kc);                        \
                float4 t4 = *(const float4*)(Tt + kc);                       \
                v.x = fmaxf(0.f, fmaf(v.x, s4.x, t4.x));                     \
                v.y = fmaxf(0.f, fmaf(v.y, s4.y, t4.y));                     \
                v.z = fmaxf(0.f, fmaf(v.z, s4.z, t4.z));                     \
                v.w = fmaxf(0.f, fmaf(v.w, s4.w, t4.w));                     \
                __half2 h0 = __floats2half2_rn(v.x, v.y);                    \
                __half2 h1 = __floats2half2_rn(v.z, v.w);                    \
                int off = row * ASTR + c4;                                   \
                *(uint32_t*)&aH[off]     = *(uint32_t*)&h0;                  \
                *(uint32_t*)&aH[off + 2] = *(uint32_t*)&h1;                  \
            }                                                                \
        } while (0)

    // ============ prologue: stage 0 in flight ============
    if (ASRC == 0) {
        CP_A_STAGE(0, 0);
    } else {
        LDG_AV(0);
    }
    CP_B_STAGE(0, 0);
    cp_commit();

    // ============ main loop (R6 schedule) ============
    for (int kt = 0; kt < NT; ++kt) {
        const int cur = kt & 1;

        if (ASRC == 1) {
            STS_AV(cur, kt * 32);   // safe: buffer last read in iter kt-2
        }
        cp_wait0();                 // drains stage kt (issued in iter kt-1)
        __syncthreads();

        // ---- prefetch stage kt+1 (full MMA block of slack)
        if (kt + 1 < NT) {
            const int nxt = (kt + 1) & 1;
            const int k0n = (kt + 1) * 32;
            if (ASRC == 0) CP_A_STAGE(nxt, k0n);
            else           LDG_AV(k0n);
            CP_B_STAGE(nxt, k0n);
            cp_commit();
        }

        // ---- MMAs on stage cur
        const __half* aH = (const __half*)(smem + AH_(cur));
        const __half* bH = (const __half*)(smem + BH_(cur));
        #pragma unroll
        for (int ks = 0; ks < 2; ++ks) {
            const int k0s = ks * 16;
            uint32_t bh[4][4];
            #pragma unroll
            for (int g = 0; g < 4; ++g) {
                int r = k0s + (lane & 15);
                int c = wn + g * 16 + (lane >> 4) * 8;
                ldsm_x4t(bh[g], s2u(&bH[r * BSTR + c]));
            }
            #pragma unroll
            for (int mi = 0; mi < 2; ++mi) {
                uint32_t ah[4];
                int r = wm + mi * 16 + (lane & 15);
                int c = k0s + (lane >> 4) * 8;
                ldsm_x4(ah, s2u(&aH[r * ASTR + c]));
                #pragma unroll
                for (int ni = 0; ni < 8; ++ni) {
                    const uint32_t* pb = &bh[ni >> 1][(ni & 1) * 2];
                    mma16816(acc[mi][ni], ah, pb);
                }
            }
        }
        __syncthreads();
    }

    // ---- epilogue: +bias, store, fused BN stats (deterministic)
    float* C = ((ASRC == 0) ? g_h1 : g_h2) + ((size_t)e * B_ + bm) * N_TOT + bn;
    const float* bias = bias_all + e * N_TOT + bn;
    #pragma unroll
    for (int ni = 0; ni < 8; ++ni) {
        int c0 = wn + ni * 8 + (lane & 3) * 2;
        float b0 = bias[c0], b1 = bias[c0 + 1];
        float ss0 = 0.f, ss1 = 0.f, qq0 = 0.f, qq1 = 0.f;
        #pragma unroll
        for (int mi = 0; mi < 2; ++mi) {
            int r0 = wm + mi * 16 + (lane >> 2);
            float v00 = acc[mi][ni][0] + b0, v01 = acc[mi][ni][1] + b1;
            float v10 = acc[mi][ni][2] + b0, v11 = acc[mi][ni][3] + b1;
            float2 w0 = { v00, v01 }, w1 = { v10, v11 };
            *(float2*)(C + (size_t)r0 * N_TOT + c0) = w0;
            *(float2*)(C + (size_t)(r0 + 8) * N_TOT + c0) = w1;
            ss0 += v00 + v10;  ss1 += v01 + v11;
            qq0 += v00 * v00 + v10 * v10;
            qq1 += v01 * v01 + v11 * v11;
        }
        #pragma unroll
        for (int o = 4; o < 32; o <<= 1) {
            ss0 += __shfl_xor_sync(0xffffffffu, ss0, o);
            ss1 += __shfl_xor_sync(0xffffffffu, ss1, o);
            qq0 += __shfl_xor_sync(0xffffffffu, qq0, o);
            qq1 += __shfl_xor_sync(0xffffffffu, qq1, o);
        }
        if (lane < 4) {
            int c = wn + ni * 8 + lane * 2;
            int rg = wid & 3;
            sred_s[rg][c] = ss0; sred_s[rg][c + 1] = ss1;
            sred_q[rg][c] = qq0; sred_q[rg][c + 1] = qq1;
        }
    }
    __syncthreads();
    if (tid < 128) {
        float s = sred_s[0][tid] + sred_s[1][tid] + sred_s[2][tid] + sred_s[3][tid];
        float q = sred_q[0][tid] + sred_q[1][tid] + sred_q[2][tid] + sred_q[3][tid];
        size_t idx = ((size_t)e * N_TOT + bn + tid) * NSLAB + blockIdx.y;
        g_psum[idx] = s;
        g_psq[idx]  = q;
    }
}

// ---------------------------------------------------------------------------
// fp32 -> fp16 round (x and weights)
// ---------------------------------------------------------------------------
__global__ __launch_bounds__(256) void round_f16(
    const float* __restrict__ src, __half* __restrict__ dh, size_t n8)
{
    size_t i = (size_t)blockIdx.x * 256 + threadIdx.x;
    if (i >= n8) return;
    const float4* s = (const float4*)src + i * 2;
    float4 v0 = s[0], v1 = s[1];
    __half2 h0 = __floats2half2_rn(v0.x, v0.y);
    __half2 h1 = __floats2half2_rn(v0.z, v0.w);
    __half2 h2 = __floats2half2_rn(v1.x, v1.y);
    __half2 h3 = __floats2half2_rn(v1.z, v1.w);
    uint4 h = { *(uint32_t*)&h0, *(uint32_t*)&h1, *(uint32_t*)&h2, *(uint32_t*)&h3 };
    ((uint4*)dh)[i] = h;
}

// ---------------------------------------------------------------------------
// Gates (measured 140us): 4 rows per warp, scalar X loads.
// ---------------------------------------------------------------------------
__global__ __launch_bounds__(256) void gates_kernel(
    const float* __restrict__ X, const float* __restrict__ Wg,
    const float* __restrict__ bg)
{
    int warp = (blockIdx.x * blockDim.x + threadIdx.x) >> 5;
    int lane = threadIdx.x & 31;
    int r0 = warp * 4;
    if (r0 >= B_) return;
    const float* x0 = X + (size_t)(r0 + 0) * D_;
    const float* x1 = X + (size_t)(r0 + 1) * D_;
    const float* x2 = X + (size_t)(r0 + 2) * D_;
    const float* x3 = X + (size_t)(r0 + 3) * D_;

    float acc[4][16];
    #pragma unroll
    for (int r = 0; r < 4; ++r)
        #pragma unroll
        for (int i = 0; i < 16; ++i) acc[r][i] = 0.f;

    for (int d = lane; d < D_; d += 32) {
        float xv0 = x0[d], xv1 = x1[d], xv2 = x2[d], xv3 = x3[d];
        #pragma unroll
        for (int t = 0; t < T_; ++t) {
            const float* wr = Wg + ((size_t)t * D_ + d) * E_;
            float4 w0 = *(const float4*)wr;
            float4 w1 = *(const float4*)(wr + 4);
            float wv[8] = { w0.x, w0.y, w0.z, w0.w, w1.x, w1.y, w1.z, w1.w };
            #pragma unroll
            for (int ee = 0; ee < 8; ++ee) {
                acc[0][t*8+ee] = fmaf(xv0, wv[ee], acc[0][t*8+ee]);
                acc[1][t*8+ee] = fmaf(xv1, wv[ee], acc[1][t*8+ee]);
                acc[2][t*8+ee] = fmaf(xv2, wv[ee], acc[2][t*8+ee]);
                acc[3][t*8+ee] = fmaf(xv3, wv[ee], acc[3][t*8+ee]);
            }
        }
    }
    #pragma unroll
    for (int r = 0; r < 4; ++r)
        #pragma unroll
        for (int i = 0; i < 16; ++i)
            #pragma unroll
            for (int o = 16; o > 0; o >>= 1)
                acc[r][i] += __shfl_xor_sync(0xffffffffu, acc[r][i], o);

    if (lane < 4) {
        #pragma unroll
        for (int r = 0; r < 4; ++r) {
            if (lane == r) {
                #pragma unroll
                for (int t = 0; t < T_; ++t) {
                    float v[8], m = -1e30f;
                    #pragma unroll
                    for (int e = 0; e < 8; ++e) {
                        v[e] = acc[r][t*8+e] + bg[t*8+e];
                        m = fmaxf(m, v[e]);
                    }
                    float s = 0.f;
                    #pragma unroll
                    for (int e = 0; e < 8; ++e) { v[e] = expf(v[e] - m); s += v[e]; }
                    float inv = 1.f / s;
                    #pragma unroll
                    for (int e = 0; e < 8; ++e)
                        g_gates[((size_t)t * B_ + r0 + r) * E_ + e] = v[e] * inv;
                }
            }
        }
    }
}

// ---------------------------------------------------------------------------
// Combine per-mblock stats -> BN scale/shift (deterministic, 256 slabs)
// ---------------------------------------------------------------------------
__global__ __launch_bounds__(256) void stats_combine(
    int which, int Hc, const float* __restrict__ gamma,
    const float* __restrict__ beta)
{
    int i = blockIdx.x * 256 + threadIdx.x;
    if (i >= E_ * Hc) return;
    const float* ps = g_psum + (size_t)i * NSLAB;
    const float* pq = g_psq  + (size_t)i * NSLAB;
    float s = 0.f, q = 0.f;
    for (int j = 0; j < NSLAB; ++j) { s += ps[j]; q += pq[j]; }
    const float invB = 1.f / (float)B_;
    float mu  = s * invB;
    float var = q * invB - mu * mu;
    float inv = rsqrtf(var + 1e-5f);
    float gg = gamma[i], bb = beta[i];
    float* Sd = (which == 0) ? g_s1 : g_s2;
    float* Td = (which == 0) ? g_t1 : g_t2;
    Sd[i] = gg * inv;
    Td[i] = bb - gg * mu * inv;
}

// ---------------------------------------------------------------------------
// Final: out[t,b,e*H2+k] = relu(BN2(g_h2[e,b,k])) * gates[t,b,e]
// ---------------------------------------------------------------------------
__global__ __launch_bounds__(256) void final_kernel(float* __restrict__ out)
{
    size_t idx = (size_t)blockIdx.x * blockDim.x + threadIdx.x;
    int k4 = (int)(idx & 63);
    int b  = (int)((idx >> 6) & (B_ - 1));
    int e  = (int)(idx >> 21);
    int k  = k4 * 4;

    float4 h  = *(const float4*)(g_h2 + (((size_t)e * B_ + b) * H2_ + k));
    float4 s  = *(const float4*)(g_s2 + e * H2_ + k);
    float4 tt = *(const float4*)(g_t2 + e * H2_ + k);
    float4 y;
    y.x = fmaxf(0.f, fmaf(h.x, s.x, tt.x));
    y.y = fmaxf(0.f, fmaf(h.y, s.y, tt.y));
    y.z = fmaxf(0.f, fmaf(h.z, s.z, tt.z));
    y.w = fmaxf(0.f, fmaf(h.w, s.w, tt.w));

    float ga = g_gates[(size_t)b * E_ + e];
    float gb = g_gates[(size_t)B_ * E_ + (size_t)b * E_ + e];

    size_t o0 = (size_t)b * (E_ * H2_) + e * H2_ + k;
    size_t o1 = (size_t)B_ * (E_ * H2_) + o0;
    float4 v0 = { y.x * ga, y.y * ga, y.z * ga, y.w * ga };
    float4 v1 = { y.x * gb, y.y * gb, y.z * gb, y.w * gb };
    *(float4*)(out + o0) = v0;
    *(float4*)(out + o1) = v1;
}

// ---------------------------------------------------------------------------
extern "C" void kernel_launch(void* const* d_in, const int* in_sizes, int n_in,
                              void* d_out, int out_size)
{
    const float* x   = (const float*)d_in[0];
    const float* W1  = (const float*)d_in[1];
    const float* b1  = (const float*)d_in[2];
    const float* g1  = (const float*)d_in[3];
    const float* be1 = (const float*)d_in[4];
    const float* W2  = (const float*)d_in[5];
    const float* b2  = (const float*)d_in[6];
    const float* g2  = (const float*)d_in[7];
    const float* be2 = (const float*)d_in[8];
    const float* Wg  = (const float*)d_in[9];
    const float* bg  = (const float*)d_in[10];
    float* out = (float*)d_out;

    cudaFuncSetAttribute(gemm_hmma<D_, H1_, 0, 4>,
        cudaFuncAttributeMaxDynamicSharedMemorySize, SMEM_BYTES);
    cudaFuncSetAttribute(gemm_hmma<H1_, H2_, 1, 2>,
        cudaFuncAttributeMaxDynamicSharedMemorySize, SMEM_BYTES);

    // ---- fp16 rounds
    {
        __half *xh, *w1h, *w2h;
        cudaGetSymbolAddress((void**)&xh,  g_xh);
        cudaGetSymbolAddress((void**)&w1h, g_w1h);
        cudaGetSymbolAddress((void**)&w2h, g_w2h);
        size_t nx = (size_t)B_ * D_ / 8;
        size_t n1 = (size_t)E_ * D_ * H1_ / 8;
        size_t n2 = (size_t)E_ * H1_ * H2_ / 8;
        round_f16<<<(unsigned)((nx + 255) / 256), 256>>>(x,  xh,  nx);
        round_f16<<<(unsigned)((n1 + 255) / 256), 256>>>(W1, w1h, n1);
        round_f16<<<(unsigned)((n2 + 255) / 256), 256>>>(W2, w2h, n2);
    }

    gates_kernel<<<B_ / 32, 256>>>(x, Wg, bg);

    gemm_hmma<D_, H1_, 0, 4>
        <<<dim3(4 * E_, B_ / 128), 256, SMEM_BYTES>>>(b1);
    stats_combine<<<(E_ * H1_ + 255) / 256, 256>>>(0, H1_, g1, be1);

    gemm_hmma<H1_, H2_, 1, 2>
        <<<dim3(2 * E_, B_ / 128), 256, SMEM_BYTES>>>(b2);
    stats_combine<<<(E_ * H2_ + 255) / 256, 256>>>(1, H2_, g2, be2);

    final_kernel<<<(unsigned)((size_t)E_ * B_ * (H2_ / 4) / 256), 256>>>(out);
}

// round 10
// speedup vs baseline: 1.5862x; 1.0071x over previous
#include <cuda_runtime.h>
#include <cuda_fp16.h>
#include <cstdint>

#define B_   32768
#define D_   1472
#define E_   8
#define H1_  512
#define H2_  256
#define T_   2
#define NSLAB 256          // one stats slab per 128-row m-block

// ---------------- scratch (static device arrays; no cudaMalloc) ------------
__device__ __half g_h1[(size_t)E_ * B_ * H1_];   // fp16 pre-BN layer-1 out
__device__ __half g_h2[(size_t)E_ * B_ * H2_];   // fp16 pre-BN layer-2 out
__device__ float g_gates[(size_t)T_ * B_ * E_];
__device__ float g_psum[(size_t)E_ * H1_ * NSLAB];
__device__ float g_psq [(size_t)E_ * H1_ * NSLAB];
__device__ float g_s1[E_ * H1_], g_t1[E_ * H1_];
__device__ float g_s2[E_ * H2_], g_t2[E_ * H2_];
// fp16 rounded operands
__device__ __half g_xh[(size_t)B_ * D_];
__device__ __half g_w1h[(size_t)E_ * D_ * H1_];
__device__ __half g_w2h[(size_t)E_ * H1_ * H2_];

// ---------------- PTX helpers ----------------------------------------------
__device__ __forceinline__ uint32_t s2u(const void* p) {
    return (uint32_t)__cvta_generic_to_shared(p);
}
__device__ __forceinline__ void ldsm_x4(uint32_t* r, uint32_t a) {
    asm volatile("ldmatrix.sync.aligned.m8n8.x4.shared.b16 {%0,%1,%2,%3}, [%4];"
        : "=r"(r[0]), "=r"(r[1]), "=r"(r[2]), "=r"(r[3]) : "r"(a));
}
__device__ __forceinline__ void ldsm_x4t(uint32_t* r, uint32_t a) {
    asm volatile("ldmatrix.sync.aligned.m8n8.x4.trans.shared.b16 {%0,%1,%2,%3}, [%4];"
        : "=r"(r[0]), "=r"(r[1]), "=r"(r[2]), "=r"(r[3]) : "r"(a));
}
__device__ __forceinline__ void mma16816(float* d, const uint32_t* a, const uint32_t* b) {
    asm volatile("mma.sync.aligned.m16n8k16.row.col.f32.f16.f16.f32 "
        "{%0,%1,%2,%3}, {%4,%5,%6,%7}, {%8,%9}, {%0,%1,%2,%3};"
        : "+f"(d[0]), "+f"(d[1]), "+f"(d[2]), "+f"(d[3])
        : "r"(a[0]), "r"(a[1]), "r"(a[2]), "r"(a[3]), "r"(b[0]), "r"(b[1]));
}
__device__ __forceinline__ void cp16(uint32_t dst, const void* src) {
    asm volatile("cp.async.cg.shared.global [%0], [%1], 16;"
        :: "r"(dst), "l"(src) : "memory");
}
__device__ __forceinline__ void cp_commit() {
    asm volatile("cp.async.commit_group;" ::: "memory");
}
__device__ __forceinline__ void cp_wait0() {
    asm volatile("cp.async.wait_group 0;" ::: "memory");
}

// ---------------- SMEM layout (bytes), 2 stages ------------------------------
#define ASTR 40
#define BSTR 136
#define STG_SZ 18944
#define AH_(b) ((b) * STG_SZ)
#define BH_(b) ((b) * STG_SZ + 10240)
#define SMEM_BYTES (2 * STG_SZ)   // 37888 -> 2 CTAs/SM

// ---------------------------------------------------------------------------
// Pure fp16 HMMA GEMM, 2-stage cp.async, 2 CTAs/SM, warp tile m32 x n64,
// fused deterministic BN batch stats, fp16 C stores.
//  ASRC 0: A = g_xh, C -> g_h1, W -> g_w1h
//  ASRC 1: A = relu(BN1(g_h1)) fused during staging (fp16 in), C -> g_h2
// ---------------------------------------------------------------------------
template<int K_TOT, int N_TOT, int ASRC, int NB>
__global__ __launch_bounds__(256, 2) void gemm_hmma(
    const float* __restrict__ bias_all)
{
    extern __shared__ char smem[];
    __shared__ float sred_s[4][128];
    __shared__ float sred_q[4][128];
    const uint32_t sb = s2u(smem);
    const int tid  = threadIdx.x;
    const int lane = tid & 31;
    const int wid  = tid >> 5;
    const int wm   = (wid & 3) * 32;   // 4 warp rows of 32
    const int wn   = (wid >> 2) * 64;  // 2 warp cols of 64

    const int e  = blockIdx.x / NB;
    const int bn = (blockIdx.x % NB) * 128;
    const int bm = blockIdx.y * 128;

    const __half* Ah = g_xh + (size_t)bm * K_TOT;                    // ASRC==0
    const __half* Af = g_h1 + ((size_t)e * B_ + bm) * (size_t)K_TOT; // ASRC==1
    const __half* Wh =
        ((ASRC == 0) ? g_w1h : g_w2h) + (size_t)e * K_TOT * N_TOT + bn;
    const float* S  = g_s1 + e * K_TOT;
    const float* Tt = g_t1 + e * K_TOT;

    float acc[2][8][4];
    #pragma unroll
    for (int i = 0; i < 2; ++i)
        #pragma unroll
        for (int j = 0; j < 8; ++j)
            #pragma unroll
            for (int r = 0; r < 4; ++r) acc[i][j][r] = 0.f;

    constexpr int NT = K_TOT / 32;
    uint4 av[2];   // ASRC==1 register staging: 16 halves per thread

    #define CP_A_STAGE(stg, k0)                                              \
        do {                                                                 \
            _Pragma("unroll")                                                \
            for (int i = 0; i < 2; ++i) {                                    \
                int cc = tid + i * 256;                                      \
                int row = cc >> 2, k4 = cc & 3;                              \
                cp16(sb + AH_(stg) + row * 80 + k4 * 16,                     \
                     Ah + (size_t)row * K_TOT + (k0) + k4 * 8);              \
            }                                                                \
        } while (0)
    #define CP_B_STAGE(stg, k0)                                              \
        do {                                                                 \
            _Pragma("unroll")                                                \
            for (int i = 0; i < 2; ++i) {                                    \
                int cc = tid + i * 256;                                      \
                int kr = cc >> 4, n16 = cc & 15;                             \
                cp16(sb + BH_(stg) + kr * 272 + n16 * 16,                    \
                     Wh + (size_t)((k0) + kr) * N_TOT + n16 * 8);            \
            }                                                                \
        } while (0)
    // A tile = 128 rows x 32 halves = 512 uint4; 2 per thread.
    #define LDG_AV(k0)                                                       \
        do {                                                                 \
            _Pragma("unroll")                                                \
            for (int i = 0; i < 2; ++i) {                                    \
                int idx = tid + i * 256;                                     \
                int row = idx >> 2, q = idx & 3;                             \
                av[i] = *(const uint4*)(Af + (size_t)row * K_TOT             \
                                           + (k0) + q * 8);                  \
            }                                                                \
        } while (0)
    #define STS_AV(stg, k0)                                                  \
        do {                                                                 \
            __half* aH = (__half*)(smem + AH_(stg));                         \
            _Pragma("unroll")                                                \
            for (int i = 0; i < 2; ++i) {                                    \
                int idx = tid + i * 256;                                     \
                int row = idx >> 2, q = idx & 3;                             \
                int kc = (k0) + q * 8;                                       \
                float4 s0 = *(const float4*)(S + kc);                        \
                float4 s1 = *(const float4*)(S + kc + 4);                    \
                float4 t0 = *(const float4*)(Tt + kc);                       \
                float4 t1 = *(const float4*)(Tt + kc + 4);                   \
                const __half2* hp = (const __half2*)&av[i];                  \
                float2 f0 = __half22float2(hp[0]);                           \
                float2 f1 = __half22float2(hp[1]);                           \
                float2 f2 = __half22float2(hp[2]);                           \
                float2 f3 = __half22float2(hp[3]);                           \
                f0.x = fmaxf(0.f, fmaf(f0.x, s0.x, t0.x));                   \
                f0.y = fmaxf(0.f, fmaf(f0.y, s0.y, t0.y));                   \
                f1.x = fmaxf(0.f, fmaf(f1.x, s0.z, t0.z));                   \
                f1.y = fmaxf(0.f, fmaf(f1.y, s0.w, t0.w));                   \
                f2.x = fmaxf(0.f, fmaf(f2.x, s1.x, t1.x));                   \
                f2.y = fmaxf(0.f, fmaf(f2.y, s1.y, t1.y));                   \
                f3.x = fmaxf(0.f, fmaf(f3.x, s1.z, t1.z));                   \
                f3.y = fmaxf(0.f, fmaf(f3.y, s1.w, t1.w));                   \
                __half2 o0 = __floats2half2_rn(f0.x, f0.y);                  \
                __half2 o1 = __floats2half2_rn(f1.x, f1.y);                  \
                __half2 o2 = __floats2half2_rn(f2.x, f2.y);                  \
                __half2 o3 = __floats2half2_rn(f3.x, f3.y);                  \
                uint4 pk = { *(uint32_t*)&o0, *(uint32_t*)&o1,               \
                             *(uint32_t*)&o2, *(uint32_t*)&o3 };             \
                *(uint4*)(aH + row * ASTR + q * 8) = pk;                     \
            }                                                                \
        } while (0)

    // ============ prologue: stage 0 in flight ============
    if (ASRC == 0) {
        CP_A_STAGE(0, 0);
    } else {
        LDG_AV(0);
    }
    CP_B_STAGE(0, 0);
    cp_commit();

    // ============ main loop (R6 schedule) ============
    for (int kt = 0; kt < NT; ++kt) {
        const int cur = kt & 1;

        if (ASRC == 1) {
            STS_AV(cur, kt * 32);
        }
        cp_wait0();
        __syncthreads();

        if (kt + 1 < NT) {
            const int nxt = (kt + 1) & 1;
            const int k0n = (kt + 1) * 32;
            if (ASRC == 0) CP_A_STAGE(nxt, k0n);
            else           LDG_AV(k0n);
            CP_B_STAGE(nxt, k0n);
            cp_commit();
        }

        const __half* aH = (const __half*)(smem + AH_(cur));
        const __half* bH = (const __half*)(smem + BH_(cur));
        #pragma unroll
        for (int ks = 0; ks < 2; ++ks) {
            const int k0s = ks * 16;
            uint32_t bh[4][4];
            #pragma unroll
            for (int g = 0; g < 4; ++g) {
                int r = k0s + (lane & 15);
                int c = wn + g * 16 + (lane >> 4) * 8;
                ldsm_x4t(bh[g], s2u(&bH[r * BSTR + c]));
            }
            #pragma unroll
            for (int mi = 0; mi < 2; ++mi) {
                uint32_t ah[4];
                int r = wm + mi * 16 + (lane & 15);
                int c = k0s + (lane >> 4) * 8;
                ldsm_x4(ah, s2u(&aH[r * ASTR + c]));
                #pragma unroll
                for (int ni = 0; ni < 8; ++ni) {
                    const uint32_t* pb = &bh[ni >> 1][(ni & 1) * 2];
                    mma16816(acc[mi][ni], ah, pb);
                }
            }
        }
        __syncthreads();
    }

    // ---- epilogue: +bias, fp16 store, fused BN stats (fp32, deterministic)
    __half* C = ((ASRC == 0) ? g_h1 : g_h2) + ((size_t)e * B_ + bm) * N_TOT + bn;
    const float* bias = bias_all + e * N_TOT + bn;
    #pragma unroll
    for (int ni = 0; ni < 8; ++ni) {
        int c0 = wn + ni * 8 + (lane & 3) * 2;
        float b0 = bias[c0], b1 = bias[c0 + 1];
        float ss0 = 0.f, ss1 = 0.f, qq0 = 0.f, qq1 = 0.f;
        #pragma unroll
        for (int mi = 0; mi < 2; ++mi) {
            int r0 = wm + mi * 16 + (lane >> 2);
            float v00 = acc[mi][ni][0] + b0, v01 = acc[mi][ni][1] + b1;
            float v10 = acc[mi][ni][2] + b0, v11 = acc[mi][ni][3] + b1;
            __half2 p0 = __floats2half2_rn(v00, v01);
            __half2 p1 = __floats2half2_rn(v10, v11);
            *(uint32_t*)(C + (size_t)r0 * N_TOT + c0) = *(uint32_t*)&p0;
            *(uint32_t*)(C + (size_t)(r0 + 8) * N_TOT + c0) = *(uint32_t*)&p1;
            ss0 += v00 + v10;  ss1 += v01 + v11;
            qq0 += v00 * v00 + v10 * v10;
            qq1 += v01 * v01 + v11 * v11;
        }
        #pragma unroll
        for (int o = 4; o < 32; o <<= 1) {
            ss0 += __shfl_xor_sync(0xffffffffu, ss0, o);
            ss1 += __shfl_xor_sync(0xffffffffu, ss1, o);
            qq0 += __shfl_xor_sync(0xffffffffu, qq0, o);
            qq1 += __shfl_xor_sync(0xffffffffu, qq1, o);
        }
        if (lane < 4) {
            int c = wn + ni * 8 + lane * 2;
            int rg = wid & 3;
            sred_s[rg][c] = ss0; sred_s[rg][c + 1] = ss1;
            sred_q[rg][c] = qq0; sred_q[rg][c + 1] = qq1;
        }
    }
    __syncthreads();
    if (tid < 128) {
        float s = sred_s[0][tid] + sred_s[1][tid] + sred_s[2][tid] + sred_s[3][tid];
        float q = sred_q[0][tid] + sred_q[1][tid] + sred_q[2][tid] + sred_q[3][tid];
        size_t idx = ((size_t)e * N_TOT + bn + tid) * NSLAB + blockIdx.y;
        g_psum[idx] = s;
        g_psq[idx]  = q;
    }
}

// ---------------------------------------------------------------------------
// fp32 -> fp16 round (x and weights)
// ---------------------------------------------------------------------------
__global__ __launch_bounds__(256) void round_f16(
    const float* __restrict__ src, __half* __restrict__ dh, size_t n8)
{
    size_t i = (size_t)blockIdx.x * 256 + threadIdx.x;
    if (i >= n8) return;
    const float4* s = (const float4*)src + i * 2;
    float4 v0 = s[0], v1 = s[1];
    __half2 h0 = __floats2half2_rn(v0.x, v0.y);
    __half2 h1 = __floats2half2_rn(v0.z, v0.w);
    __half2 h2 = __floats2half2_rn(v1.x, v1.y);
    __half2 h3 = __floats2half2_rn(v1.z, v1.w);
    uint4 h = { *(uint32_t*)&h0, *(uint32_t*)&h1, *(uint32_t*)&h2, *(uint32_t*)&h3 };
    ((uint4*)dh)[i] = h;
}

// ---------------------------------------------------------------------------
// Gates: 2 rows per warp (fewer regs -> ~50% occ), scalar X loads.
// ---------------------------------------------------------------------------
__global__ __launch_bounds__(256) void gates_kernel(
    const float* __restrict__ X, const float* __restrict__ Wg,
    const float* __restrict__ bg)
{
    int warp = (blockIdx.x * blockDim.x + threadIdx.x) >> 5;
    int lane = threadIdx.x & 31;
    int r0 = warp * 2;
    if (r0 >= B_) return;
    const float* x0 = X + (size_t)(r0 + 0) * D_;
    const float* x1 = X + (size_t)(r0 + 1) * D_;

    float acc[2][16];
    #pragma unroll
    for (int r = 0; r < 2; ++r)
        #pragma unroll
        for (int i = 0; i < 16; ++i) acc[r][i] = 0.f;

    for (int d = lane; d < D_; d += 32) {
        float xv0 = x0[d], xv1 = x1[d];
        #pragma unroll
        for (int t = 0; t < T_; ++t) {
            const float* wr = Wg + ((size_t)t * D_ + d) * E_;
            float4 w0 = *(const float4*)wr;
            float4 w1 = *(const float4*)(wr + 4);
            float wv[8] = { w0.x, w0.y, w0.z, w0.w, w1.x, w1.y, w1.z, w1.w };
            #pragma unroll
            for (int ee = 0; ee < 8; ++ee) {
                acc[0][t*8+ee] = fmaf(xv0, wv[ee], acc[0][t*8+ee]);
                acc[1][t*8+ee] = fmaf(xv1, wv[ee], acc[1][t*8+ee]);
            }
        }
    }
    #pragma unroll
    for (int r = 0; r < 2; ++r)
        #pragma unroll
        for (int i = 0; i < 16; ++i)
            #pragma unroll
            for (int o = 16; o > 0; o >>= 1)
                acc[r][i] += __shfl_xor_sync(0xffffffffu, acc[r][i], o);

    if (lane < 2) {
        int r = lane;
        #pragma unroll
        for (int t = 0; t < T_; ++t) {
            float v[8], m = -1e30f;
            #pragma unroll
            for (int e = 0; e < 8; ++e) {
                v[e] = acc[r][t*8+e] + bg[t*8+e];
                m = fmaxf(m, v[e]);
            }
            float s = 0.f;
            #pragma unroll
            for (int e = 0; e < 8; ++e) { v[e] = expf(v[e] - m); s += v[e]; }
            float inv = 1.f / s;
            #pragma unroll
            for (int e = 0; e < 8; ++e)
                g_gates[((size_t)t * B_ + r0 + r) * E_ + e] = v[e] * inv;
        }
    }
}

// ---------------------------------------------------------------------------
// Combine per-mblock stats -> BN scale/shift (deterministic, 256 slabs)
// ---------------------------------------------------------------------------
__global__ __launch_bounds__(256) void stats_combine(
    int which, int Hc, const float* __restrict__ gamma,
    const float* __restrict__ beta)
{
    int i = blockIdx.x * 256 + threadIdx.x;
    if (i >= E_ * Hc) return;
    const float* ps = g_psum + (size_t)i * NSLAB;
    const float* pq = g_psq  + (size_t)i * NSLAB;
    float s = 0.f, q = 0.f;
    for (int j = 0; j < NSLAB; ++j) { s += ps[j]; q += pq[j]; }
    const float invB = 1.f / (float)B_;
    float mu  = s * invB;
    float var = q * invB - mu * mu;
    float inv = rsqrtf(var + 1e-5f);
    float gg = gamma[i], bb = beta[i];
    float* Sd = (which == 0) ? g_s1 : g_s2;
    float* Td = (which == 0) ? g_t1 : g_t2;
    Sd[i] = gg * inv;
    Td[i] = bb - gg * mu * inv;
}

// ---------------------------------------------------------------------------
// Final: out[t,b,e*H2+k] = relu(BN2(g_h2[e,b,k])) * gates[t,b,e]
// 8 halves of h2 per thread -> 2 tasks x 2 float4 stores.
// ---------------------------------------------------------------------------
__global__ __launch_bounds__(256) void final_kernel(float* __restrict__ out)
{
    size_t idx = (size_t)blockIdx.x * blockDim.x + threadIdx.x;  // E*B*32
    int k8 = (int)(idx & 31);              // H2/8 = 32
    int b  = (int)((idx >> 5) & (B_ - 1));
    int e  = (int)(idx >> 20);
    int k  = k8 * 8;

    uint4 hv = *(const uint4*)(g_h2 + (((size_t)e * B_ + b) * H2_ + k));
    const __half2* hp = (const __half2*)&hv;
    float4 s0 = *(const float4*)(g_s2 + e * H2_ + k);
    float4 s1 = *(const float4*)(g_s2 + e * H2_ + k + 4);
    float4 t0 = *(const float4*)(g_t2 + e * H2_ + k);
    float4 t1 = *(const float4*)(g_t2 + e * H2_ + k + 4);

    float2 f0 = __half22float2(hp[0]);
    float2 f1 = __half22float2(hp[1]);
    float2 f2 = __half22float2(hp[2]);
    float2 f3 = __half22float2(hp[3]);
    float y[8];
    y[0] = fmaxf(0.f, fmaf(f0.x, s0.x, t0.x));
    y[1] = fmaxf(0.f, fmaf(f0.y, s0.y, t0.y));
    y[2] = fmaxf(0.f, fmaf(f1.x, s0.z, t0.z));
    y[3] = fmaxf(0.f, fmaf(f1.y, s0.w, t0.w));
    y[4] = fmaxf(0.f, fmaf(f2.x, s1.x, t1.x));
    y[5] = fmaxf(0.f, fmaf(f2.y, s1.y, t1.y));
    y[6] = fmaxf(0.f, fmaf(f3.x, s1.z, t1.z));
    y[7] = fmaxf(0.f, fmaf(f3.y, s1.w, t1.w));

    float ga = g_gates[(size_t)b * E_ + e];
    float gb = g_gates[(size_t)B_ * E_ + (size_t)b * E_ + e];

    size_t o0 = (size_t)b * (E_ * H2_) + e * H2_ + k;
    size_t o1 = (size_t)B_ * (E_ * H2_) + o0;
    float4 a0 = { y[0]*ga, y[1]*ga, y[2]*ga, y[3]*ga };
    float4 a1 = { y[4]*ga, y[5]*ga, y[6]*ga, y[7]*ga };
    float4 b0 = { y[0]*gb, y[1]*gb, y[2]*gb, y[3]*gb };
    float4 b1 = { y[4]*gb, y[5]*gb, y[6]*gb, y[7]*gb };
    *(float4*)(out + o0)     = a0;
    *(float4*)(out + o0 + 4) = a1;
    *(float4*)(out + o1)     = b0;
    *(float4*)(out + o1 + 4) = b1;
}

// ---------------------------------------------------------------------------
extern "C" void kernel_launch(void* const* d_in, const int* in_sizes, int n_in,
                              void* d_out, int out_size)
{
    const float* x   = (const float*)d_in[0];
    const float* W1  = (const float*)d_in[1];
    const float* b1  = (const float*)d_in[2];
    const float* g1  = (const float*)d_in[3];
    const float* be1 = (const float*)d_in[4];
    const float* W2  = (const float*)d_in[5];
    const float* b2  = (const float*)d_in[6];
    const float* g2  = (const float*)d_in[7];
    const float* be2 = (const float*)d_in[8];
    const float* Wg  = (const float*)d_in[9];
    const float* bg  = (const float*)d_in[10];
    float* out = (float*)d_out;

    cudaFuncSetAttribute(gemm_hmma<D_, H1_, 0, 4>,
        cudaFuncAttributeMaxDynamicSharedMemorySize, SMEM_BYTES);
    cudaFuncSetAttribute(gemm_hmma<H1_, H2_, 1, 2>,
        cudaFuncAttributeMaxDynamicSharedMemorySize, SMEM_BYTES);

    // ---- fp16 rounds
    {
        __half *xh, *w1h, *w2h;
        cudaGetSymbolAddress((void**)&xh,  g_xh);
        cudaGetSymbolAddress((void**)&w1h, g_w1h);
        cudaGetSymbolAddress((void**)&w2h, g_w2h);
        size_t nx = (size_t)B_ * D_ / 8;
        size_t n1 = (size_t)E_ * D_ * H1_ / 8;
        size_t n2 = (size_t)E_ * H1_ * H2_ / 8;
        round_f16<<<(unsigned)((nx + 255) / 256), 256>>>(x,  xh,  nx);
        round_f16<<<(unsigned)((n1 + 255) / 256), 256>>>(W1, w1h, n1);
        round_f16<<<(unsigned)((n2 + 255) / 256), 256>>>(W2, w2h, n2);
    }

    gates_kernel<<<B_ / 16, 256>>>(x, Wg, bg);

    gemm_hmma<D_, H1_, 0, 4>
        <<<dim3(4 * E_, B_ / 128), 256, SMEM_BYTES>>>(b1);
    stats_combine<<<(E_ * H1_ + 255) / 256, 256>>>(0, H1_, g1, be1);

    gemm_hmma<H1_, H2_, 1, 2>
        <<<dim3(2 * E_, B_ / 128), 256, SMEM_BYTES>>>(b2);
    stats_combine<<<(E_ * H2_ + 255) / 256, 256>>>(1, H2_, g2, be2);

    final_kernel<<<(unsigned)((size_t)E_ * B_ * 32 / 256), 256>>>(out);
}

// round 11
// speedup vs baseline: 1.6622x; 1.0479x over previous
#include <cuda_runtime.h>
#include <cuda_fp16.h>
#include <cstdint>

#define B_   32768
#define D_   1472
#define E_   8
#define H1_  512
#define H2_  256
#define T_   2
#define NSLAB 256          // one stats slab per 128-row m-block

// ---------------- scratch (static device arrays; no cudaMalloc) ------------
__device__ __half g_h1[(size_t)E_ * B_ * H1_];   // fp16 pre-BN layer-1 out
__device__ __half g_h2[(size_t)E_ * B_ * H2_];   // fp16 pre-BN layer-2 out
__device__ float g_gates[(size_t)T_ * B_ * E_];
__device__ float g_psum[(size_t)E_ * H1_ * NSLAB];
__device__ float g_psq [(size_t)E_ * H1_ * NSLAB];
__device__ float g_s1[E_ * H1_], g_t1[E_ * H1_];
__device__ float g_s2[E_ * H2_], g_t2[E_ * H2_];
// fp16 rounded operands
__device__ __half g_xh[(size_t)B_ * D_];
__device__ __half g_w1h[(size_t)E_ * D_ * H1_];
__device__ __half g_w2h[(size_t)E_ * H1_ * H2_];

// ---------------- PTX helpers ----------------------------------------------
__device__ __forceinline__ uint32_t s2u(const void* p) {
    return (uint32_t)__cvta_generic_to_shared(p);
}
__device__ __forceinline__ void ldsm_x4(uint32_t* r, uint32_t a) {
    asm volatile("ldmatrix.sync.aligned.m8n8.x4.shared.b16 {%0,%1,%2,%3}, [%4];"
        : "=r"(r[0]), "=r"(r[1]), "=r"(r[2]), "=r"(r[3]) : "r"(a));
}
__device__ __forceinline__ void ldsm_x4t(uint32_t* r, uint32_t a) {
    asm volatile("ldmatrix.sync.aligned.m8n8.x4.trans.shared.b16 {%0,%1,%2,%3}, [%4];"
        : "=r"(r[0]), "=r"(r[1]), "=r"(r[2]), "=r"(r[3]) : "r"(a));
}
__device__ __forceinline__ void mma16816(float* d, const uint32_t* a, const uint32_t* b) {
    asm volatile("mma.sync.aligned.m16n8k16.row.col.f32.f16.f16.f32 "
        "{%0,%1,%2,%3}, {%4,%5,%6,%7}, {%8,%9}, {%0,%1,%2,%3};"
        : "+f"(d[0]), "+f"(d[1]), "+f"(d[2]), "+f"(d[3])
        : "r"(a[0]), "r"(a[1]), "r"(a[2]), "r"(a[3]), "r"(b[0]), "r"(b[1]));
}
__device__ __forceinline__ void cp16(uint32_t dst, const void* src) {
    asm volatile("cp.async.cg.shared.global [%0], [%1], 16;"
        :: "r"(dst), "l"(src) : "memory");
}
__device__ __forceinline__ void cp_commit() {
    asm volatile("cp.async.commit_group;" ::: "memory");
}
__device__ __forceinline__ void cp_wait0() {
    asm volatile("cp.async.wait_group 0;" ::: "memory");
}

// ---------------- SMEM layout (bytes), 2 stages, K-chunk 64 ------------------
// A tile: 128 rows x 64 fp16, padded row = 72 elems (144 B) -> 18432 B
// B tile: 64 rows x 128 fp16, padded row = 136 elems (272B) -> 17408 B
#define ASTR 72
#define BSTR 136
#define STG_SZ 35840
#define AH_(b) ((b) * STG_SZ)
#define BH_(b) ((b) * STG_SZ + 18432)
#define SMEM_BYTES (2 * STG_SZ)   // 71680 -> 2 CTAs/SM (143 KB + static)

// ---------------------------------------------------------------------------
// Pure fp16 HMMA GEMM body, K-chunk 64, 2-stage cp.async, 2 CTAs/SM,
// warp tile m32 x n64, fused deterministic BN batch stats, fp16 C stores.
// ---------------------------------------------------------------------------
template<int K_TOT, int N_TOT, int ASRC, int NB>
__device__ __forceinline__ void gemm_body(
    const float* __restrict__ bias_all, int bx, int by, char* smem)
{
    __shared__ float sred_s[4][128];
    __shared__ float sred_q[4][128];
    const uint32_t sb = s2u(smem);
    const int tid  = threadIdx.x;
    const int lane = tid & 31;
    const int wid  = tid >> 5;
    const int wm   = (wid & 3) * 32;   // 4 warp rows of 32
    const int wn   = (wid >> 2) * 64;  // 2 warp cols of 64

    const int e  = bx / NB;
    const int bn = (bx % NB) * 128;
    const int bm = by * 128;

    const __half* Ah = g_xh + (size_t)bm * K_TOT;                    // ASRC==0
    const __half* Af = g_h1 + ((size_t)e * B_ + bm) * (size_t)K_TOT; // ASRC==1
    const __half* Wh =
        ((ASRC == 0) ? g_w1h : g_w2h) + (size_t)e * K_TOT * N_TOT + bn;
    const float* S  = g_s1 + e * K_TOT;
    const float* Tt = g_t1 + e * K_TOT;

    float acc[2][8][4];
    #pragma unroll
    for (int i = 0; i < 2; ++i)
        #pragma unroll
        for (int j = 0; j < 8; ++j)
            #pragma unroll
            for (int r = 0; r < 4; ++r) acc[i][j][r] = 0.f;

    constexpr int NT = K_TOT / 64;
    uint4 av[4];   // ASRC==1 register staging: 32 halves per thread

    #define CP_A_STAGE(stg, k0)                                              \
        do {                                                                 \
            _Pragma("unroll")                                                \
            for (int i = 0; i < 4; ++i) {                                    \
                int cc = tid + i * 256;                                      \
                int row = cc >> 3, k8 = cc & 7;                              \
                cp16(sb + AH_(stg) + row * 144 + k8 * 16,                    \
                     Ah + (size_t)row * K_TOT + (k0) + k8 * 8);              \
            }                                                                \
        } while (0)
    #define CP_B_STAGE(stg, k0)                                              \
        do {                                                                 \
            _Pragma("unroll")                                                \
            for (int i = 0; i < 4; ++i) {                                    \
                int cc = tid + i * 256;                                      \
                int kr = cc >> 4, n16 = cc & 15;                             \
                cp16(sb + BH_(stg) + kr * 272 + n16 * 16,                    \
                     Wh + (size_t)((k0) + kr) * N_TOT + n16 * 8);            \
            }                                                                \
        } while (0)
    #define LDG_AV(k0)                                                       \
        do {                                                                 \
            _Pragma("unroll")                                                \
            for (int i = 0; i < 4; ++i) {                                    \
                int idx = tid + i * 256;                                     \
                int row = idx >> 3, q = idx & 7;                             \
                av[i] = *(const uint4*)(Af + (size_t)row * K_TOT             \
                                           + (k0) + q * 8);                  \
            }                                                                \
        } while (0)
    #define STS_AV(stg, k0)                                                  \
        do {                                                                 \
            __half* aH = (__half*)(smem + AH_(stg));                         \
            _Pragma("unroll")                                                \
            for (int i = 0; i < 4; ++i) {                                    \
                int idx = tid + i * 256;                                     \
                int row = idx >> 3, q = idx & 7;                             \
                int kc = (k0) + q * 8;                                       \
                float4 s0 = *(const float4*)(S + kc);                        \
                float4 s1 = *(const float4*)(S + kc + 4);                    \
                float4 t0 = *(const float4*)(Tt + kc);                       \
                float4 t1 = *(const float4*)(Tt + kc + 4);                   \
                const __half2* hp = (const __half2*)&av[i];                  \
                float2 f0 = __half22float2(hp[0]);                           \
                float2 f1 = __half22float2(hp[1]);                           \
                float2 f2 = __half22float2(hp[2]);                           \
                float2 f3 = __half22float2(hp[3]);                           \
                f0.x = fmaxf(0.f, fmaf(f0.x, s0.x, t0.x));                   \
                f0.y = fmaxf(0.f, fmaf(f0.y, s0.y, t0.y));                   \
                f1.x = fmaxf(0.f, fmaf(f1.x, s0.z, t0.z));                   \
                f1.y = fmaxf(0.f, fmaf(f1.y, s0.w, t0.w));                   \
                f2.x = fmaxf(0.f, fmaf(f2.x, s1.x, t1.x));                   \
                f2.y = fmaxf(0.f, fmaf(f2.y, s1.y, t1.y));                   \
                f3.x = fmaxf(0.f, fmaf(f3.x, s1.z, t1.z));                   \
                f3.y = fmaxf(0.f, fmaf(f3.y, s1.w, t1.w));                   \
                __half2 o0 = __floats2half2_rn(f0.x, f0.y);                  \
                __half2 o1 = __floats2half2_rn(f1.x, f1.y);                  \
                __half2 o2 = __floats2half2_rn(f2.x, f2.y);                  \
                __half2 o3 = __floats2half2_rn(f3.x, f3.y);                  \
                uint4 pk = { *(uint32_t*)&o0, *(uint32_t*)&o1,               \
                             *(uint32_t*)&o2, *(uint32_t*)&o3 };             \
                *(uint4*)(aH + row * ASTR + q * 8) = pk;                     \
            }                                                                \
        } while (0)

    // ============ prologue: stage 0 in flight ============
    if (ASRC == 0) {
        CP_A_STAGE(0, 0);
    } else {
        LDG_AV(0);
    }
    CP_B_STAGE(0, 0);
    cp_commit();

    // ============ main loop ============
    for (int kt = 0; kt < NT; ++kt) {
        const int cur = kt & 1;

        if (ASRC == 1) {
            STS_AV(cur, kt * 64);
        }
        cp_wait0();
        __syncthreads();

        if (kt + 1 < NT) {
            const int nxt = (kt + 1) & 1;
            const int k0n = (kt + 1) * 64;
            if (ASRC == 0) CP_A_STAGE(nxt, k0n);
            else           LDG_AV(k0n);
            CP_B_STAGE(nxt, k0n);
            cp_commit();
        }

        const __half* aH = (const __half*)(smem + AH_(cur));
        const __half* bH = (const __half*)(smem + BH_(cur));
        #pragma unroll
        for (int ks = 0; ks < 4; ++ks) {
            const int k0s = ks * 16;
            uint32_t bh[4][4];
            #pragma unroll
            for (int g = 0; g < 4; ++g) {
                int r = k0s + (lane & 15);
                int c = wn + g * 16 + (lane >> 4) * 8;
                ldsm_x4t(bh[g], s2u(&bH[r * BSTR + c]));
            }
            #pragma unroll
            for (int mi = 0; mi < 2; ++mi) {
                uint32_t ah[4];
                int r = wm + mi * 16 + (lane & 15);
                int c = k0s + (lane >> 4) * 8;
                ldsm_x4(ah, s2u(&aH[r * ASTR + c]));
                #pragma unroll
                for (int ni = 0; ni < 8; ++ni) {
                    const uint32_t* pb = &bh[ni >> 1][(ni & 1) * 2];
                    mma16816(acc[mi][ni], ah, pb);
                }
            }
        }
        __syncthreads();
    }

    // ---- epilogue: +bias, fp16 store, fused BN stats (fp32, deterministic)
    __half* C = ((ASRC == 0) ? g_h1 : g_h2) + ((size_t)e * B_ + bm) * N_TOT + bn;
    const float* bias = bias_all + e * N_TOT + bn;
    #pragma unroll
    for (int ni = 0; ni < 8; ++ni) {
        int c0 = wn + ni * 8 + (lane & 3) * 2;
        float b0 = bias[c0], b1 = bias[c0 + 1];
        float ss0 = 0.f, ss1 = 0.f, qq0 = 0.f, qq1 = 0.f;
        #pragma unroll
        for (int mi = 0; mi < 2; ++mi) {
            int r0 = wm + mi * 16 + (lane >> 2);
            float v00 = acc[mi][ni][0] + b0, v01 = acc[mi][ni][1] + b1;
            float v10 = acc[mi][ni][2] + b0, v11 = acc[mi][ni][3] + b1;
            __half2 p0 = __floats2half2_rn(v00, v01);
            __half2 p1 = __floats2half2_rn(v10, v11);
            *(uint32_t*)(C + (size_t)r0 * N_TOT + c0) = *(uint32_t*)&p0;
            *(uint32_t*)(C + (size_t)(r0 + 8) * N_TOT + c0) = *(uint32_t*)&p1;
            ss0 += v00 + v10;  ss1 += v01 + v11;
            qq0 += v00 * v00 + v10 * v10;
            qq1 += v01 * v01 + v11 * v11;
        }
        #pragma unroll
        for (int o = 4; o < 32; o <<= 1) {
            ss0 += __shfl_xor_sync(0xffffffffu, ss0, o);
            ss1 += __shfl_xor_sync(0xffffffffu, ss1, o);
            qq0 += __shfl_xor_sync(0xffffffffu, qq0, o);
            qq1 += __shfl_xor_sync(0xffffffffu, qq1, o);
        }
        if (lane < 4) {
            int c = wn + ni * 8 + lane * 2;
            int rg = wid & 3;
            sred_s[rg][c] = ss0; sred_s[rg][c + 1] = ss1;
            sred_q[rg][c] = qq0; sred_q[rg][c + 1] = qq1;
        }
    }
    __syncthreads();
    if (tid < 128) {
        float s = sred_s[0][tid] + sred_s[1][tid] + sred_s[2][tid] + sred_s[3][tid];
        float q = sred_q[0][tid] + sred_q[1][tid] + sred_q[2][tid] + sred_q[3][tid];
        size_t idx = ((size_t)e * N_TOT + bn + tid) * NSLAB + by;
        g_psum[idx] = s;
        g_psq[idx]  = q;
    }
    #undef CP_A_STAGE
    #undef CP_B_STAGE
    #undef LDG_AV
    #undef STS_AV
}

// ---------------------------------------------------------------------------
// Gates body: 2 rows per warp, scalar X loads (R10-measured path).
// ---------------------------------------------------------------------------
__device__ void gates_body(
    int gbid, const float* __restrict__ X, const float* __restrict__ Wg,
    const float* __restrict__ bg)
{
    int warp = (gbid * 256 + threadIdx.x) >> 5;
    int lane = threadIdx.x & 31;
    int r0 = warp * 2;
    if (r0 >= B_) return;
    const float* x0 = X + (size_t)(r0 + 0) * D_;
    const float* x1 = X + (size_t)(r0 + 1) * D_;

    float acc[2][16];
    #pragma unroll
    for (int r = 0; r < 2; ++r)
        #pragma unroll
        for (int i = 0; i < 16; ++i) acc[r][i] = 0.f;

    for (int d = lane; d < D_; d += 32) {
        float xv0 = x0[d], xv1 = x1[d];
        #pragma unroll
        for (int t = 0; t < T_; ++t) {
            const float* wr = Wg + ((size_t)t * D_ + d) * E_;
            float4 w0 = *(const float4*)wr;
            float4 w1 = *(const float4*)(wr + 4);
            float wv[8] = { w0.x, w0.y, w0.z, w0.w, w1.x, w1.y, w1.z, w1.w };
            #pragma unroll
            for (int ee = 0; ee < 8; ++ee) {
                acc[0][t*8+ee] = fmaf(xv0, wv[ee], acc[0][t*8+ee]);
                acc[1][t*8+ee] = fmaf(xv1, wv[ee], acc[1][t*8+ee]);
            }
        }
    }
    #pragma unroll
    for (int r = 0; r < 2; ++r)
        #pragma unroll
        for (int i = 0; i < 16; ++i)
            #pragma unroll
            for (int o = 16; o > 0; o >>= 1)
                acc[r][i] += __shfl_xor_sync(0xffffffffu, acc[r][i], o);

    if (lane < 2) {
        int r = lane;
        #pragma unroll
        for (int t = 0; t < T_; ++t) {
            float v[8], m = -1e30f;
            #pragma unroll
            for (int e = 0; e < 8; ++e) {
                v[e] = acc[r][t*8+e] + bg[t*8+e];
                m = fmaxf(m, v[e]);
            }
            float s = 0.f;
            #pragma unroll
            for (int e = 0; e < 8; ++e) { v[e] = expf(v[e] - m); s += v[e]; }
            float inv = 1.f / s;
            #pragma unroll
            for (int e = 0; e < 8; ++e)
                g_gates[((size_t)t * B_ + r0 + r) * E_ + e] = v[e] * inv;
        }
    }
}

// ---------------------------------------------------------------------------
// Fused launch: GEMM1 blocks [0, 8192) + gates blocks [8192, 10240)
// ---------------------------------------------------------------------------
#define G1_BLOCKS (4 * E_ * (B_ / 128))   // 8192
#define GATE_BLOCKS (B_ / 16)             // 2048

__global__ __launch_bounds__(256, 2) void gemm1_gates(
    const float* __restrict__ b1, const float* __restrict__ X,
    const float* __restrict__ Wg, const float* __restrict__ bg)
{
    extern __shared__ char smem[];
    int bid = blockIdx.x;
    if (bid < G1_BLOCKS) {
        gemm_body<D_, H1_, 0, 4>(b1, bid & 31, bid >> 5, smem);
    } else {
        gates_body(bid - G1_BLOCKS, X, Wg, bg);
    }
}

__global__ __launch_bounds__(256, 2) void gemm2_kernel(
    const float* __restrict__ b2)
{
    extern __shared__ char smem[];
    gemm_body<H1_, H2_, 1, 2>(b2, blockIdx.x, blockIdx.y, smem);
}

// ---------------------------------------------------------------------------
// Merged fp32 -> fp16 rounds (x, W1, W2) in one launch
// ---------------------------------------------------------------------------
#define NX8 ((size_t)B_ * D_ / 8)
#define N18 ((size_t)E_ * D_ * H1_ / 8)
#define N28 ((size_t)E_ * H1_ * H2_ / 8)

__global__ __launch_bounds__(256) void round_all(
    const float* __restrict__ x, const float* __restrict__ W1,
    const float* __restrict__ W2)
{
    size_t i = (size_t)blockIdx.x * 256 + threadIdx.x;
    const float* src;
    __half* dst;
    size_t j;
    if (i < NX8)             { src = x;  dst = g_xh;  j = i; }
    else if (i < NX8 + N18)  { src = W1; dst = g_w1h; j = i - NX8; }
    else if (i < NX8 + N18 + N28) { src = W2; dst = g_w2h; j = i - NX8 - N18; }
    else return;
    const float4* s = (const float4*)src + j * 2;
    float4 v0 = s[0], v1 = s[1];
    __half2 h0 = __floats2half2_rn(v0.x, v0.y);
    __half2 h1 = __floats2half2_rn(v0.z, v0.w);
    __half2 h2 = __floats2half2_rn(v1.x, v1.y);
    __half2 h3 = __floats2half2_rn(v1.z, v1.w);
    uint4 h = { *(uint32_t*)&h0, *(uint32_t*)&h1, *(uint32_t*)&h2, *(uint32_t*)&h3 };
    ((uint4*)dst)[j] = h;
}

// ---------------------------------------------------------------------------
// Combine per-mblock stats -> BN scale/shift (deterministic, 256 slabs)
// ---------------------------------------------------------------------------
__global__ __launch_bounds__(256) void stats_combine(
    int which, int Hc, const float* __restrict__ gamma,
    const float* __restrict__ beta)
{
    int i = blockIdx.x * 256 + threadIdx.x;
    if (i >= E_ * Hc) return;
    const float* ps = g_psum + (size_t)i * NSLAB;
    const float* pq = g_psq  + (size_t)i * NSLAB;
    float s = 0.f, q = 0.f;
    for (int j = 0; j < NSLAB; ++j) { s += ps[j]; q += pq[j]; }
    const float invB = 1.f / (float)B_;
    float mu  = s * invB;
    float var = q * invB - mu * mu;
    float inv = rsqrtf(var + 1e-5f);
    float gg = gamma[i], bb = beta[i];
    float* Sd = (which == 0) ? g_s1 : g_s2;
    float* Td = (which == 0) ? g_t1 : g_t2;
    Sd[i] = gg * inv;
    Td[i] = bb - gg * mu * inv;
}

// ---------------------------------------------------------------------------
// Final: out[t,b,e*H2+k] = relu(BN2(g_h2[e,b,k])) * gates[t,b,e]
// ---------------------------------------------------------------------------
__global__ __launch_bounds__(256) void final_kernel(float* __restrict__ out)
{
    size_t idx = (size_t)blockIdx.x * blockDim.x + threadIdx.x;  // E*B*32
    int k8 = (int)(idx & 31);
    int b  = (int)((idx >> 5) & (B_ - 1));
    int e  = (int)(idx >> 20);
    int k  = k8 * 8;

    uint4 hv = *(const uint4*)(g_h2 + (((size_t)e * B_ + b) * H2_ + k));
    const __half2* hp = (const __half2*)&hv;
    float4 s0 = *(const float4*)(g_s2 + e * H2_ + k);
    float4 s1 = *(const float4*)(g_s2 + e * H2_ + k + 4);
    float4 t0 = *(const float4*)(g_t2 + e * H2_ + k);
    float4 t1 = *(const float4*)(g_t2 + e * H2_ + k + 4);

    float2 f0 = __half22float2(hp[0]);
    float2 f1 = __half22float2(hp[1]);
    float2 f2 = __half22float2(hp[2]);
    float2 f3 = __half22float2(hp[3]);
    float y[8];
    y[0] = fmaxf(0.f, fmaf(f0.x, s0.x, t0.x));
    y[1] = fmaxf(0.f, fmaf(f0.y, s0.y, t0.y));
    y[2] = fmaxf(0.f, fmaf(f1.x, s0.z, t0.z));
    y[3] = fmaxf(0.f, fmaf(f1.y, s0.w, t0.w));
    y[4] = fmaxf(0.f, fmaf(f2.x, s1.x, t1.x));
    y[5] = fmaxf(0.f, fmaf(f2.y, s1.y, t1.y));
    y[6] = fmaxf(0.f, fmaf(f3.x, s1.z, t1.z));
    y[7] = fmaxf(0.f, fmaf(f3.y, s1.w, t1.w));

    float ga = g_gates[(size_t)b * E_ + e];
    float gb = g_gates[(size_t)B_ * E_ + (size_t)b * E_ + e];

    size_t o0 = (size_t)b * (E_ * H2_) + e * H2_ + k;
    size_t o1 = (size_t)B_ * (E_ * H2_) + o0;
    float4 a0 = { y[0]*ga, y[1]*ga, y[2]*ga, y[3]*ga };
    float4 a1 = { y[4]*ga, y[5]*ga, y[6]*ga, y[7]*ga };
    float4 b0 = { y[0]*gb, y[1]*gb, y[2]*gb, y[3]*gb };
    float4 b1 = { y[4]*gb, y[5]*gb, y[6]*gb, y[7]*gb };
    *(float4*)(out + o0)     = a0;
    *(float4*)(out + o0 + 4) = a1;
    *(float4*)(out + o1)     = b0;
    *(float4*)(out + o1 + 4) = b1;
}

// ---------------------------------------------------------------------------
extern "C" void kernel_launch(void* const* d_in, const int* in_sizes, int n_in,
                              void* d_out, int out_size)
{
    const float* x   = (const float*)d_in[0];
    const float* W1  = (const float*)d_in[1];
    const float* b1  = (const float*)d_in[2];
    const float* g1  = (const float*)d_in[3];
    const float* be1 = (const float*)d_in[4];
    const float* W2  = (const float*)d_in[5];
    const float* b2  = (const float*)d_in[6];
    const float* g2  = (const float*)d_in[7];
    const float* be2 = (const float*)d_in[8];
    const float* Wg  = (const float*)d_in[9];
    const float* bg  = (const float*)d_in[10];
    float* out = (float*)d_out;

    cudaFuncSetAttribute(gemm1_gates,
        cudaFuncAttributeMaxDynamicSharedMemorySize, SMEM_BYTES);
    cudaFuncSetAttribute(gemm2_kernel,
        cudaFuncAttributeMaxDynamicSharedMemorySize, SMEM_BYTES);

    size_t ntot = NX8 + N18 + N28;
    round_all<<<(unsigned)((ntot + 255) / 256), 256>>>(x, W1, W2);

    gemm1_gates<<<G1_BLOCKS + GATE_BLOCKS, 256, SMEM_BYTES>>>(b1, x, Wg, bg);
    stats_combine<<<(E_ * H1_ + 255) / 256, 256>>>(0, H1_, g1, be1);

    gemm2_kernel<<<dim3(2 * E_, B_ / 128), 256, SMEM_BYTES>>>(b2);
    stats_combine<<<(E_ * H2_ + 255) / 256, 256>>>(1, H2_, g2, be2);

    final_kernel<<<(unsigned)((size_t)E_ * B_ * 32 / 256), 256>>>(out);
}

// round 12
// speedup vs baseline: 1.6793x; 1.0103x over previous
#include <cuda_runtime.h>
#include <cuda_fp16.h>
#include <cstdint>

#define B_   32768
#define D_   1472
#define E_   8
#define H1_  512
#define H2_  256
#define T_   2
#define NSLAB 256          // one stats slab per 128-row m-block

// ---------------- scratch (static device arrays; no cudaMalloc) ------------
__device__ __half g_h1[(size_t)E_ * B_ * H1_];   // fp16 pre-BN layer-1 out
__device__ __half g_h2[(size_t)E_ * B_ * H2_];   // fp16 pre-BN layer-2 out
__device__ float g_gates[(size_t)T_ * B_ * E_];
__device__ float g_psum[(size_t)E_ * H1_ * NSLAB];
__device__ float g_psq [(size_t)E_ * H1_ * NSLAB];
__device__ float g_s1[E_ * H1_], g_t1[E_ * H1_];
__device__ float g_s2[E_ * H2_], g_t2[E_ * H2_];
// fp16 rounded operands
__device__ __half g_xh[(size_t)B_ * D_];
__device__ __half g_w1h[(size_t)E_ * D_ * H1_];
__device__ __half g_w2h[(size_t)E_ * H1_ * H2_];

// ---------------- PTX helpers ----------------------------------------------
__device__ __forceinline__ uint32_t s2u(const void* p) {
    return (uint32_t)__cvta_generic_to_shared(p);
}
__device__ __forceinline__ void ldsm_x4(uint32_t* r, uint32_t a) {
    asm volatile("ldmatrix.sync.aligned.m8n8.x4.shared.b16 {%0,%1,%2,%3}, [%4];"
        : "=r"(r[0]), "=r"(r[1]), "=r"(r[2]), "=r"(r[3]) : "r"(a));
}
__device__ __forceinline__ void ldsm_x4t(uint32_t* r, uint32_t a) {
    asm volatile("ldmatrix.sync.aligned.m8n8.x4.trans.shared.b16 {%0,%1,%2,%3}, [%4];"
        : "=r"(r[0]), "=r"(r[1]), "=r"(r[2]), "=r"(r[3]) : "r"(a));
}
__device__ __forceinline__ void mma16816(float* d, const uint32_t* a, const uint32_t* b) {
    asm volatile("mma.sync.aligned.m16n8k16.row.col.f32.f16.f16.f32 "
        "{%0,%1,%2,%3}, {%4,%5,%6,%7}, {%8,%9}, {%0,%1,%2,%3};"
        : "+f"(d[0]), "+f"(d[1]), "+f"(d[2]), "+f"(d[3])
        : "r"(a[0]), "r"(a[1]), "r"(a[2]), "r"(a[3]), "r"(b[0]), "r"(b[1]));
}
__device__ __forceinline__ void cp16(uint32_t dst, const void* src) {
    asm volatile("cp.async.cg.shared.global [%0], [%1], 16;"
        :: "r"(dst), "l"(src) : "memory");
}
__device__ __forceinline__ void cp_commit() {
    asm volatile("cp.async.commit_group;" ::: "memory");
}
__device__ __forceinline__ void cp_wait0() {
    asm volatile("cp.async.wait_group 0;" ::: "memory");
}

// ---------------- SMEM layout (bytes), 2 stages, K-chunk 64 ------------------
#define ASTR 72
#define BSTR 136
#define STG_SZ 35840
#define AH_(b) ((b) * STG_SZ)
#define BH_(b) ((b) * STG_SZ + 18432)
#define SMEM_BYTES (2 * STG_SZ)   // 71680 -> 2 CTAs/SM

// ---------------------------------------------------------------------------
// Pure fp16 HMMA GEMM body, K-chunk 64, 2-stage cp.async, 2 CTAs/SM,
// warp tile m32 x n64, ONE barrier per ktile, fused BN stats, fp16 C stores.
// ---------------------------------------------------------------------------
template<int K_TOT, int N_TOT, int ASRC, int NB>
__device__ __forceinline__ void gemm_body(
    const float* __restrict__ bias_all, int bx, int by, char* smem)
{
    __shared__ float sred_s[4][128];
    __shared__ float sred_q[4][128];
    const uint32_t sb = s2u(smem);
    const int tid  = threadIdx.x;
    const int lane = tid & 31;
    const int wid  = tid >> 5;
    const int wm   = (wid & 3) * 32;   // 4 warp rows of 32
    const int wn   = (wid >> 2) * 64;  // 2 warp cols of 64

    const int e  = bx / NB;
    const int bn = (bx % NB) * 128;
    const int bm = by * 128;

    const __half* Ah = g_xh + (size_t)bm * K_TOT;                    // ASRC==0
    const __half* Af = g_h1 + ((size_t)e * B_ + bm) * (size_t)K_TOT; // ASRC==1
    const __half* Wh =
        ((ASRC == 0) ? g_w1h : g_w2h) + (size_t)e * K_TOT * N_TOT + bn;
    const float* S  = g_s1 + e * K_TOT;
    const float* Tt = g_t1 + e * K_TOT;

    float acc[2][8][4];
    #pragma unroll
    for (int i = 0; i < 2; ++i)
        #pragma unroll
        for (int j = 0; j < 8; ++j)
            #pragma unroll
            for (int r = 0; r < 4; ++r) acc[i][j][r] = 0.f;

    constexpr int NT = K_TOT / 64;
    uint4 av[4];   // ASRC==1 register staging: 32 halves per thread

    #define CP_A_STAGE(stg, k0)                                              \
        do {                                                                 \
            _Pragma("unroll")                                                \
            for (int i = 0; i < 4; ++i) {                                    \
                int cc = tid + i * 256;                                      \
                int row = cc >> 3, k8 = cc & 7;                              \
                cp16(sb + AH_(stg) + row * 144 + k8 * 16,                    \
                     Ah + (size_t)row * K_TOT + (k0) + k8 * 8);              \
            }                                                                \
        } while (0)
    #define CP_B_STAGE(stg, k0)                                              \
        do {                                                                 \
            _Pragma("unroll")                                                \
            for (int i = 0; i < 4; ++i) {                                    \
                int cc = tid + i * 256;                                      \
                int kr = cc >> 4, n16 = cc & 15;                             \
                cp16(sb + BH_(stg) + kr * 272 + n16 * 16,                    \
                     Wh + (size_t)((k0) + kr) * N_TOT + n16 * 8);            \
            }                                                                \
        } while (0)
    #define LDG_AV(k0)                                                       \
        do {                                                                 \
            _Pragma("unroll")                                                \
            for (int i = 0; i < 4; ++i) {                                    \
                int idx = tid + i * 256;                                     \
                int row = idx >> 3, q = idx & 7;                             \
                av[i] = *(const uint4*)(Af + (size_t)row * K_TOT             \
                                           + (k0) + q * 8);                  \
            }                                                                \
        } while (0)
    #define STS_AV(stg, k0)                                                  \
        do {                                                                 \
            __half* aH = (__half*)(smem + AH_(stg));                         \
            _Pragma("unroll")                                                \
            for (int i = 0; i < 4; ++i) {                                    \
                int idx = tid + i * 256;                                     \
                int row = idx >> 3, q = idx & 7;                             \
                int kc = (k0) + q * 8;                                       \
                float4 s0 = *(const float4*)(S + kc);                        \
                float4 s1 = *(const float4*)(S + kc + 4);                    \
                float4 t0 = *(const float4*)(Tt + kc);                       \
                float4 t1 = *(const float4*)(Tt + kc + 4);                   \
                const __half2* hp = (const __half2*)&av[i];                  \
                float2 f0 = __half22float2(hp[0]);                           \
                float2 f1 = __half22float2(hp[1]);                           \
                float2 f2 = __half22float2(hp[2]);                           \
                float2 f3 = __half22float2(hp[3]);                           \
                f0.x = fmaxf(0.f, fmaf(f0.x, s0.x, t0.x));                   \
                f0.y = fmaxf(0.f, fmaf(f0.y, s0.y, t0.y));                   \
                f1.x = fmaxf(0.f, fmaf(f1.x, s0.z, t0.z));                   \
                f1.y = fmaxf(0.f, fmaf(f1.y, s0.w, t0.w));                   \
                f2.x = fmaxf(0.f, fmaf(f2.x, s1.x, t1.x));                   \
                f2.y = fmaxf(0.f, fmaf(f2.y, s1.y, t1.y));                   \
                f3.x = fmaxf(0.f, fmaf(f3.x, s1.z, t1.z));                   \
                f3.y = fmaxf(0.f, fmaf(f3.y, s1.w, t1.w));                   \
                __half2 o0 = __floats2half2_rn(f0.x, f0.y);                  \
                __half2 o1 = __floats2half2_rn(f1.x, f1.y);                  \
                __half2 o2 = __floats2half2_rn(f2.x, f2.y);                  \
                __half2 o3 = __floats2half2_rn(f3.x, f3.y);                  \
                uint4 pk = { *(uint32_t*)&o0, *(uint32_t*)&o1,               \
                             *(uint32_t*)&o2, *(uint32_t*)&o3 };             \
                *(uint4*)(aH + row * ASTR + q * 8) = pk;                     \
            }                                                                \
        } while (0)

    // ============ prologue: stage 0 in flight ============
    if (ASRC == 0) {
        CP_A_STAGE(0, 0);
    } else {
        LDG_AV(0);
    }
    CP_B_STAGE(0, 0);
    cp_commit();

    // ============ main loop: ONE barrier per ktile ============
    // Safety: the top sync of iter kt implies all warps finished iter kt-1's
    // MMAs (buffer (kt-1)&1) and this iter's STS(cur). cp.async after the
    // sync writes buffer (kt+1)&1 == (kt-1)&1, whose readers are done; the
    // MMA block reads buffer kt&1, written before the same sync.
    for (int kt = 0; kt < NT; ++kt) {
        const int cur = kt & 1;

        if (ASRC == 1) {
            STS_AV(cur, kt * 64);
        }
        cp_wait0();
        __syncthreads();

        if (kt + 1 < NT) {
            const int nxt = (kt + 1) & 1;
            const int k0n = (kt + 1) * 64;
            if (ASRC == 0) CP_A_STAGE(nxt, k0n);
            else           LDG_AV(k0n);
            CP_B_STAGE(nxt, k0n);
            cp_commit();
        }

        const __half* aH = (const __half*)(smem + AH_(cur));
        const __half* bH = (const __half*)(smem + BH_(cur));
        #pragma unroll
        for (int ks = 0; ks < 4; ++ks) {
            const int k0s = ks * 16;
            uint32_t bh[4][4];
            #pragma unroll
            for (int g = 0; g < 4; ++g) {
                int r = k0s + (lane & 15);
                int c = wn + g * 16 + (lane >> 4) * 8;
                ldsm_x4t(bh[g], s2u(&bH[r * BSTR + c]));
            }
            #pragma unroll
            for (int mi = 0; mi < 2; ++mi) {
                uint32_t ah[4];
                int r = wm + mi * 16 + (lane & 15);
                int c = k0s + (lane >> 4) * 8;
                ldsm_x4(ah, s2u(&aH[r * ASTR + c]));
                #pragma unroll
                for (int ni = 0; ni < 8; ++ni) {
                    const uint32_t* pb = &bh[ni >> 1][(ni & 1) * 2];
                    mma16816(acc[mi][ni], ah, pb);
                }
            }
        }
        // (no trailing barrier — see proof above)
    }

    // ---- epilogue: +bias, fp16 store, fused BN stats (fp32, deterministic)
    __half* C = ((ASRC == 0) ? g_h1 : g_h2) + ((size_t)e * B_ + bm) * N_TOT + bn;
    const float* bias = bias_all + e * N_TOT + bn;
    #pragma unroll
    for (int ni = 0; ni < 8; ++ni) {
        int c0 = wn + ni * 8 + (lane & 3) * 2;
        float b0 = bias[c0], b1 = bias[c0 + 1];
        float ss0 = 0.f, ss1 = 0.f, qq0 = 0.f, qq1 = 0.f;
        #pragma unroll
        for (int mi = 0; mi < 2; ++mi) {
            int r0 = wm + mi * 16 + (lane >> 2);
            float v00 = acc[mi][ni][0] + b0, v01 = acc[mi][ni][1] + b1;
            float v10 = acc[mi][ni][2] + b0, v11 = acc[mi][ni][3] + b1;
            __half2 p0 = __floats2half2_rn(v00, v01);
            __half2 p1 = __floats2half2_rn(v10, v11);
            *(uint32_t*)(C + (size_t)r0 * N_TOT + c0) = *(uint32_t*)&p0;
            *(uint32_t*)(C + (size_t)(r0 + 8) * N_TOT + c0) = *(uint32_t*)&p1;
            ss0 += v00 + v10;  ss1 += v01 + v11;
            qq0 += v00 * v00 + v10 * v10;
            qq1 += v01 * v01 + v11 * v11;
        }
        #pragma unroll
        for (int o = 4; o < 32; o <<= 1) {
            ss0 += __shfl_xor_sync(0xffffffffu, ss0, o);
            ss1 += __shfl_xor_sync(0xffffffffu, ss1, o);
            qq0 += __shfl_xor_sync(0xffffffffu, qq0, o);
            qq1 += __shfl_xor_sync(0xffffffffu, qq1, o);
        }
        if (lane < 4) {
            int c = wn + ni * 8 + lane * 2;
            int rg = wid & 3;
            sred_s[rg][c] = ss0; sred_s[rg][c + 1] = ss1;
            sred_q[rg][c] = qq0; sred_q[rg][c + 1] = qq1;
        }
    }
    __syncthreads();
    if (tid < 128) {
        float s = sred_s[0][tid] + sred_s[1][tid] + sred_s[2][tid] + sred_s[3][tid];
        float q = sred_q[0][tid] + sred_q[1][tid] + sred_q[2][tid] + sred_q[3][tid];
        size_t idx = ((size_t)e * N_TOT + bn + tid) * NSLAB + by;
        g_psum[idx] = s;
        g_psq[idx]  = q;
    }
    #undef CP_A_STAGE
    #undef CP_B_STAGE
    #undef LDG_AV
    #undef STS_AV
}

// ---------------------------------------------------------------------------
// Gates body: 2 rows per warp, scalar X loads.
// ---------------------------------------------------------------------------
__device__ void gates_body(
    int gbid, const float* __restrict__ X, const float* __restrict__ Wg,
    const float* __restrict__ bg)
{
    int warp = (gbid * 256 + threadIdx.x) >> 5;
    int lane = threadIdx.x & 31;
    int r0 = warp * 2;
    if (r0 >= B_) return;
    const float* x0 = X + (size_t)(r0 + 0) * D_;
    const float* x1 = X + (size_t)(r0 + 1) * D_;

    float acc[2][16];
    #pragma unroll
    for (int r = 0; r < 2; ++r)
        #pragma unroll
        for (int i = 0; i < 16; ++i) acc[r][i] = 0.f;

    for (int d = lane; d < D_; d += 32) {
        float xv0 = x0[d], xv1 = x1[d];
        #pragma unroll
        for (int t = 0; t < T_; ++t) {
            const float* wr = Wg + ((size_t)t * D_ + d) * E_;
            float4 w0 = *(const float4*)wr;
            float4 w1 = *(const float4*)(wr + 4);
            float wv[8] = { w0.x, w0.y, w0.z, w0.w, w1.x, w1.y, w1.z, w1.w };
            #pragma unroll
            for (int ee = 0; ee < 8; ++ee) {
                acc[0][t*8+ee] = fmaf(xv0, wv[ee], acc[0][t*8+ee]);
                acc[1][t*8+ee] = fmaf(xv1, wv[ee], acc[1][t*8+ee]);
            }
        }
    }
    #pragma unroll
    for (int r = 0; r < 2; ++r)
        #pragma unroll
        for (int i = 0; i < 16; ++i)
            #pragma unroll
            for (int o = 16; o > 0; o >>= 1)
                acc[r][i] += __shfl_xor_sync(0xffffffffu, acc[r][i], o);

    if (lane < 2) {
        int r = lane;
        #pragma unroll
        for (int t = 0; t < T_; ++t) {
            float v[8], m = -1e30f;
            #pragma unroll
            for (int e = 0; e < 8; ++e) {
                v[e] = acc[r][t*8+e] + bg[t*8+e];
                m = fmaxf(m, v[e]);
            }
            float s = 0.f;
            #pragma unroll
            for (int e = 0; e < 8; ++e) { v[e] = expf(v[e] - m); s += v[e]; }
            float inv = 1.f / s;
            #pragma unroll
            for (int e = 0; e < 8; ++e)
                g_gates[((size_t)t * B_ + r0 + r) * E_ + e] = v[e] * inv;
        }
    }
}

// ---------------------------------------------------------------------------
// Fused launch: GEMM1 blocks [0, 8192) + gates blocks [8192, 10240)
// ---------------------------------------------------------------------------
#define G1_BLOCKS (4 * E_ * (B_ / 128))   // 8192
#define GATE_BLOCKS (B_ / 16)             // 2048

__global__ __launch_bounds__(256, 2) void gemm1_gates(
    const float* __restrict__ b1, const float* __restrict__ X,
    const float* __restrict__ Wg, const float* __restrict__ bg)
{
    extern __shared__ char smem[];
    int bid = blockIdx.x;
    if (bid < G1_BLOCKS) {
        gemm_body<D_, H1_, 0, 4>(b1, bid & 31, bid >> 5, smem);
    } else {
        gates_body(bid - G1_BLOCKS, X, Wg, bg);
    }
}

__global__ __launch_bounds__(256, 2) void gemm2_kernel(
    const float* __restrict__ b2)
{
    extern __shared__ char smem[];
    gemm_body<H1_, H2_, 1, 2>(b2, blockIdx.x, blockIdx.y, smem);
}

// ---------------------------------------------------------------------------
// Merged fp32 -> fp16 rounds (x, W1, W2) in one launch
// ---------------------------------------------------------------------------
#define NX8 ((size_t)B_ * D_ / 8)
#define N18 ((size_t)E_ * D_ * H1_ / 8)
#define N28 ((size_t)E_ * H1_ * H2_ / 8)

__global__ __launch_bounds__(256) void round_all(
    const float* __restrict__ x, const float* __restrict__ W1,
    const float* __restrict__ W2)
{
    size_t i = (size_t)blockIdx.x * 256 + threadIdx.x;
    const float* src;
    __half* dst;
    size_t j;
    if (i < NX8)             { src = x;  dst = g_xh;  j = i; }
    else if (i < NX8 + N18)  { src = W1; dst = g_w1h; j = i - NX8; }
    else if (i < NX8 + N18 + N28) { src = W2; dst = g_w2h; j = i - NX8 - N18; }
    else return;
    const float4* s = (const float4*)src + j * 2;
    float4 v0 = s[0], v1 = s[1];
    __half2 h0 = __floats2half2_rn(v0.x, v0.y);
    __half2 h1 = __floats2half2_rn(v0.z, v0.w);
    __half2 h2 = __floats2half2_rn(v1.x, v1.y);
    __half2 h3 = __floats2half2_rn(v1.z, v1.w);
    uint4 h = { *(uint32_t*)&h0, *(uint32_t*)&h1, *(uint32_t*)&h2, *(uint32_t*)&h3 };
    ((uint4*)dst)[j] = h;
}

// ---------------------------------------------------------------------------
// Combine per-mblock stats -> BN scale/shift (deterministic, 256 slabs)
// ---------------------------------------------------------------------------
__global__ __launch_bounds__(256) void stats_combine(
    int which, int Hc, const float* __restrict__ gamma,
    const float* __restrict__ beta)
{
    int i = blockIdx.x * 256 + threadIdx.x;
    if (i >= E_ * Hc) return;
    const float* ps = g_psum + (size_t)i * NSLAB;
    const float* pq = g_psq  + (size_t)i * NSLAB;
    float s = 0.f, q = 0.f;
    for (int j = 0; j < NSLAB; ++j) { s += ps[j]; q += pq[j]; }
    const float invB = 1.f / (float)B_;
    float mu  = s * invB;
    float var = q * invB - mu * mu;
    float inv = rsqrtf(var + 1e-5f);
    float gg = gamma[i], bb = beta[i];
    float* Sd = (which == 0) ? g_s1 : g_s2;
    float* Td = (which == 0) ? g_t1 : g_t2;
    Sd[i] = gg * inv;
    Td[i] = bb - gg * mu * inv;
}

// ---------------------------------------------------------------------------
// Final: out[t,b,e*H2+k] = relu(BN2(g_h2[e,b,k])) * gates[t,b,e]
// ---------------------------------------------------------------------------
__global__ __launch_bounds__(256) void final_kernel(float* __restrict__ out)
{
    size_t idx = (size_t)blockIdx.x * blockDim.x + threadIdx.x;  // E*B*32
    int k8 = (int)(idx & 31);
    int b  = (int)((idx >> 5) & (B_ - 1));
    int e  = (int)(idx >> 20);
    int k  = k8 * 8;

    uint4 hv = *(const uint4*)(g_h2 + (((size_t)e * B_ + b) * H2_ + k));
    const __half2* hp = (const __half2*)&hv;
    float4 s0 = *(const float4*)(g_s2 + e * H2_ + k);
    float4 s1 = *(const float4*)(g_s2 + e * H2_ + k + 4);
    float4 t0 = *(const float4*)(g_t2 + e * H2_ + k);
    float4 t1 = *(const float4*)(g_t2 + e * H2_ + k + 4);

    float2 f0 = __half22float2(hp[0]);
    float2 f1 = __half22float2(hp[1]);
    float2 f2 = __half22float2(hp[2]);
    float2 f3 = __half22float2(hp[3]);
    float y[8];
    y[0] = fmaxf(0.f, fmaf(f0.x, s0.x, t0.x));
    y[1] = fmaxf(0.f, fmaf(f0.y, s0.y, t0.y));
    y[2] = fmaxf(0.f, fmaf(f1.x, s0.z, t0.z));
    y[3] = fmaxf(0.f, fmaf(f1.y, s0.w, t0.w));
    y[4] = fmaxf(0.f, fmaf(f2.x, s1.x, t1.x));
    y[5] = fmaxf(0.f, fmaf(f2.y, s1.y, t1.y));
    y[6] = fmaxf(0.f, fmaf(f3.x, s1.z, t1.z));
    y[7] = fmaxf(0.f, fmaf(f3.y, s1.w, t1.w));

    float ga = g_gates[(size_t)b * E_ + e];
    float gb = g_gates[(size_t)B_ * E_ + (size_t)b * E_ + e];

    size_t o0 = (size_t)b * (E_ * H2_) + e * H2_ + k;
    size_t o1 = (size_t)B_ * (E_ * H2_) + o0;
    float4 a0 = { y[0]*ga, y[1]*ga, y[2]*ga, y[3]*ga };
    float4 a1 = { y[4]*ga, y[5]*ga, y[6]*ga, y[7]*ga };
    float4 b0 = { y[0]*gb, y[1]*gb, y[2]*gb, y[3]*gb };
    float4 b1 = { y[4]*gb, y[5]*gb, y[6]*gb, y[7]*gb };
    *(float4*)(out + o0)     = a0;
    *(float4*)(out + o0 + 4) = a1;
    *(float4*)(out + o1)     = b0;
    *(float4*)(out + o1 + 4) = b1;
}

// ---------------------------------------------------------------------------
extern "C" void kernel_launch(void* const* d_in, const int* in_sizes, int n_in,
                              void* d_out, int out_size)
{
    const float* x   = (const float*)d_in[0];
    const float* W1  = (const float*)d_in[1];
    const float* b1  = (const float*)d_in[2];
    const float* g1  = (const float*)d_in[3];
    const float* be1 = (const float*)d_in[4];
    const float* W2  = (const float*)d_in[5];
    const float* b2  = (const float*)d_in[6];
    const float* g2  = (const float*)d_in[7];
    const float* be2 = (const float*)d_in[8];
    const float* Wg  = (const float*)d_in[9];
    const float* bg  = (const float*)d_in[10];
    float* out = (float*)d_out;

    cudaFuncSetAttribute(gemm1_gates,
        cudaFuncAttributeMaxDynamicSharedMemorySize, SMEM_BYTES);
    cudaFuncSetAttribute(gemm2_kernel,
        cudaFuncAttributeMaxDynamicSharedMemorySize, SMEM_BYTES);

    size_t ntot = NX8 + N18 + N28;
    round_all<<<(unsigned)((ntot + 255) / 256), 256>>>(x, W1, W2);

    gemm1_gates<<<G1_BLOCKS + GATE_BLOCKS, 256, SMEM_BYTES>>>(b1, x, Wg, bg);
    stats_combine<<<(E_ * H1_ + 255) / 256, 256>>>(0, H1_, g1, be1);

    gemm2_kernel<<<dim3(2 * E_, B_ / 128), 256, SMEM_BYTES>>>(b2);
    stats_combine<<<(E_ * H2_ + 255) / 256, 256>>>(1, H2_, g2, be2);

    final_kernel<<<(unsigned)((size_t)E_ * B_ * 32 / 256), 256>>>(out);
}